// round 11
// baseline (speedup 1.0000x reference)
#include <cuda_runtime.h>
#include <cuda_bf16.h>
#include <cstdint>
#include <math.h>

#define SEQ    3072
#define HID    1536
#define NH     12
#define HD     128
#define QKVW   4608   // 3*HID
#define INTER  13696
#define MAXL   1024
#define EPS    1e-6f

// ===================== PTX helpers (baseline PTX only) ======================
__device__ __forceinline__ uint32_t smem_to_u32(const void* p) {
    uint32_t a;
    asm("{ .reg .u64 t; cvta.to.shared.u64 t, %1; cvt.u32.u64 %0, t; }"
        : "=r"(a) : "l"(p));
    return a;
}
__device__ __forceinline__ void cp_async16(uint32_t dst, const void* src) {
    asm volatile("cp.async.cg.shared.global [%0], [%1], 16;"
                 :: "r"(dst), "l"(src) : "memory");
}
#define CP_COMMIT() asm volatile("cp.async.commit_group;" ::: "memory")
#define CP_WAIT1()  asm volatile("cp.async.wait_group 1;" ::: "memory")
#define CP_WAIT0()  asm volatile("cp.async.wait_group 0;" ::: "memory")

__device__ __forceinline__ void ldsm4(uint32_t* r, uint32_t addr) {
    asm volatile("ldmatrix.sync.aligned.m8n8.x4.shared.b16 {%0,%1,%2,%3}, [%4];"
                 : "=r"(r[0]), "=r"(r[1]), "=r"(r[2]), "=r"(r[3]) : "r"(addr));
}
__device__ __forceinline__ void ldsm2(uint32_t* r, uint32_t addr) {
    asm volatile("ldmatrix.sync.aligned.m8n8.x2.shared.b16 {%0,%1}, [%2];"
                 : "=r"(r[0]), "=r"(r[1]) : "r"(addr));
}
__device__ __forceinline__ void ldsm2t(uint32_t* r, uint32_t addr) {
    asm volatile("ldmatrix.sync.aligned.m8n8.x2.trans.shared.b16 {%0,%1}, [%2];"
                 : "=r"(r[0]), "=r"(r[1]) : "r"(addr));
}
__device__ __forceinline__ void mma_bf16(float* c, const uint32_t* a, const uint32_t* b) {
    asm volatile("mma.sync.aligned.m16n8k16.row.col.f32.bf16.bf16.f32 "
                 "{%0,%1,%2,%3}, {%4,%5,%6,%7}, {%8,%9}, {%0,%1,%2,%3};"
                 : "+f"(c[0]), "+f"(c[1]), "+f"(c[2]), "+f"(c[3])
                 : "r"(a[0]), "r"(a[1]), "r"(a[2]), "r"(a[3]),
                   "r"(b[0]), "r"(b[1]));
}
__device__ __forceinline__ void mma_s8(int32_t* c, const uint32_t* a, const uint32_t* b) {
    asm volatile("mma.sync.aligned.m16n8k32.row.col.s32.s8.s8.s32 "
                 "{%0,%1,%2,%3}, {%4,%5,%6,%7}, {%8,%9}, {%0,%1,%2,%3};"
                 : "+r"(c[0]), "+r"(c[1]), "+r"(c[2]), "+r"(c[3])
                 : "r"(a[0]), "r"(a[1]), "r"(a[2]), "r"(a[3]),
                   "r"(b[0]), "r"(b[1]));
}
__device__ __forceinline__ void split_bf16(float v, __nv_bfloat16& h, __nv_bfloat16& l) {
    h = __float2bfloat16(v);
    l = __float2bfloat16(v - __bfloat162float(h));
}
// int8 hi/lo quantization: v ~= s*(h + l/254)/127, inv127s = 127/s
__device__ __forceinline__ void quant8(float v, float inv127s, int8_t& h8, int8_t& l8) {
    float xs = v * inv127s;
    xs = fminf(fmaxf(xs, -127.f), 127.f);
    float hf = rintf(xs);
    h8 = (int8_t)(int)hf;
    l8 = (int8_t)(int)rintf((xs - hf) * 254.f);
}
__device__ __forceinline__ uint32_t sw128(uint32_t off) {
    return off ^ ((off >> 3) & 0x70);
}

// ===================== scratch =============================================
__device__ float g_qkv   [SEQ * QKVW];
__device__ float g_scores[(size_t)NH * SEQ * MAXL];
__device__ float g_hid2  [SEQ * HID];
__device__ float g_up    [(size_t)SEQ * INTER];   // up, then act (in-place)

__device__ __nv_bfloat16 g_hn_h [SEQ * HID],  g_hn_l [SEQ * HID];
__device__ __nv_bfloat16 g_at_h [SEQ * HID],  g_at_l [SEQ * HID];

__device__ __nv_bfloat16 g_q_h[(size_t)NH * SEQ * HD], g_q_l[(size_t)NH * SEQ * HD];
__device__ __nv_bfloat16 g_k_h[(size_t)NH * SEQ * HD], g_k_l[(size_t)NH * SEQ * HD];
__device__ __nv_bfloat16 g_v_h[(size_t)NH * SEQ * HD], g_v_l[(size_t)NH * SEQ * HD];
__device__ __nv_bfloat16 g_p_h[(size_t)NH * SEQ * MAXL], g_p_l[(size_t)NH * SEQ * MAXL];

__device__ __nv_bfloat16 g_wqkv_h [(size_t)QKVW * HID],  g_wqkv_l [(size_t)QKVW * HID];
__device__ __nv_bfloat16 g_wproj_h[(size_t)HID * HID],   g_wproj_l[(size_t)HID * HID];

// int8 MLP operands
__device__ int8_t g_a8h[SEQ * HID], g_a8l[SEQ * HID];                 // h2n q8
__device__ float  g_sa[SEQ];
__device__ int8_t g_act8h[(size_t)SEQ * INTER], g_act8l[(size_t)SEQ * INTER];
__device__ float  g_sact[SEQ];
__device__ int8_t g_wg8h[(size_t)INTER * HID], g_wg8l[(size_t)INTER * HID];
__device__ int8_t g_wu8h[(size_t)INTER * HID], g_wu8l[(size_t)INTER * HID];
__device__ int8_t g_wd8h[(size_t)HID * INTER], g_wd8l[(size_t)HID * INTER];
__device__ float  g_sg[INTER], g_su[INTER], g_sd[HID];

// ===================== weight transpose + split (bf16, qkv/proj) ===========
__global__ void wconv_t(const float* __restrict__ W, __nv_bfloat16* __restrict__ Th,
                        __nv_bfloat16* __restrict__ Tl, int K, int N) {
    __shared__ float ts[32][33];
    int n0 = blockIdx.x * 32, k0 = blockIdx.y * 32;
    int tx = threadIdx.x, ty = threadIdx.y;   // 32 x 8
#pragma unroll
    for (int r = 0; r < 32; r += 8)
        ts[ty + r][tx] = W[(size_t)(k0 + ty + r) * N + n0 + tx];
    __syncthreads();
#pragma unroll
    for (int r = 0; r < 32; r += 8) {
        float v = ts[tx][ty + r];
        __nv_bfloat16 h, l;
        split_bf16(v, h, l);
        size_t o = (size_t)(n0 + ty + r) * K + k0 + tx;
        Th[o] = h;
        Tl[o] = l;
    }
}

// ===================== weight transpose + int8 quant (MLP weights) ==========
// W: [K,N] fp32 -> Th8/Tl8: [N,K] int8, s[N] = column max
__global__ void wconv_q8(const float* __restrict__ W, int8_t* __restrict__ Th,
                         int8_t* __restrict__ Tl, float* __restrict__ s, int K, int N) {
    int n0 = blockIdx.x * 32;
    int tx = threadIdx.x, ty = threadIdx.y;   // 32 x 8
    __shared__ float smax[8][32];
    __shared__ float scol[32];
    float m = 0.f;
    for (int r = ty; r < K; r += 8)
        m = fmaxf(m, fabsf(W[(size_t)r * N + n0 + tx]));
    smax[ty][tx] = m;
    __syncthreads();
    if (ty == 0) {
        float mm = smax[0][tx];
#pragma unroll
        for (int j = 1; j < 8; j++) mm = fmaxf(mm, smax[j][tx]);
        mm = fmaxf(mm, 1e-30f);
        scol[tx] = 127.f / mm;
        s[n0 + tx] = mm;
    }
    __syncthreads();
    __shared__ float ts[32][33];
    for (int k0 = 0; k0 < K; k0 += 32) {
#pragma unroll
        for (int r = 0; r < 32; r += 8)
            ts[ty + r][tx] = W[(size_t)(k0 + ty + r) * N + n0 + tx];
        __syncthreads();
#pragma unroll
        for (int r = 0; r < 32; r += 8) {
            int n = ty + r;
            float v = ts[tx][n];            // W[k0+tx][n0+n]
            int8_t h8, l8;
            quant8(v, scol[n], h8, l8);
            size_t o = (size_t)(n0 + n) * K + k0 + tx;
            Th[o] = h8;
            Tl[o] = l8;
        }
        __syncthreads();
    }
}

// ===================== bf16 GEMM machinery (k=64 chunks) ====================
__device__ __forceinline__ void load_chunk(
    uint32_t buf, int tid,
    const __nv_bfloat16* __restrict__ Ah, const __nv_bfloat16* __restrict__ Al,
    const __nv_bfloat16* __restrict__ Bh, const __nv_bfloat16* __restrict__ Bl,
    int m0, int n0, int k0, int K) {
#pragma unroll
    for (int t = 0; t < 16; t++) {
        int idx = tid + t * 256;
        int tile = idx >> 10;
        int w = idx & 1023;
        int r = w >> 3, c8 = w & 7;
        const __nv_bfloat16* src =
            (tile == 0 ? Ah : tile == 1 ? Al : tile == 2 ? Bh : Bl);
        int row = (tile < 2 ? m0 : n0) + r;
        uint32_t dst = buf + tile * 16384 + sw128((uint32_t)(r * 128 + c8 * 16));
        cp_async16(dst, src + (size_t)row * K + k0 + c8 * 8);
    }
}

__device__ __forceinline__ void compute_chunk(
    uint32_t buf, int wm, int wn, int lane, float acc[4][4][4]) {
    const uint32_t bAh = buf;
    const uint32_t bAl = buf + 16384;
    const uint32_t bBh = buf + 32768;
    const uint32_t bBl = buf + 49152;
#pragma unroll
    for (int ks = 0; ks < 4; ks++) {
        uint32_t bh[4][2], bl[4][2];
#pragma unroll
        for (int ni = 0; ni < 4; ni++) {
            uint32_t rowB = wn * 32 + ni * 8 + (lane & 7);
            uint32_t kb = ks * 32 + ((lane >> 3) & 1) * 16;
            uint32_t sw = sw128(rowB * 128 + kb);
            ldsm2(bh[ni], bBh + sw);
            ldsm2(bl[ni], bBl + sw);
        }
#pragma unroll
        for (int mi = 0; mi < 4; mi++) {
            uint32_t rowA = wm * 64 + mi * 16 + (lane & 15);
            uint32_t kb = ks * 32 + (lane >> 4) * 16;
            uint32_t sw = sw128(rowA * 128 + kb);
            uint32_t ah[4], al[4];
            ldsm4(ah, bAh + sw);
            ldsm4(al, bAl + sw);
#pragma unroll
            for (int ni = 0; ni < 4; ni++) {
                mma_bf16(acc[mi][ni], ah, bh[ni]);
                mma_bf16(acc[mi][ni], ah, bl[ni]);
                mma_bf16(acc[mi][ni], al, bh[ni]);
            }
        }
    }
}

// ===================== bf16x3 GEMM (fp32 out, optional residual) ============
__global__ __launch_bounds__(256, 1) void gemm_bf16x3(
    const __nv_bfloat16* __restrict__ Ah, const __nv_bfloat16* __restrict__ Al,
    const __nv_bfloat16* __restrict__ Bh, const __nv_bfloat16* __restrict__ Bl,
    const float* __restrict__ R, float* __restrict__ C, int N, int K) {
    extern __shared__ char smem[];
    const uint32_t sb = smem_to_u32(smem);
    const int tid = threadIdx.x;
    const int wid = tid >> 5;
    const int lane = tid & 31;
    const int wm = wid & 1;
    const int wn = wid >> 1;
    const int m0 = blockIdx.x * 128;
    const int n0 = blockIdx.y * 128;

    float acc[4][4][4];
#pragma unroll
    for (int i = 0; i < 4; i++)
#pragma unroll
        for (int j = 0; j < 4; j++)
#pragma unroll
            for (int k = 0; k < 4; k++) acc[i][j][k] = 0.f;

    const int nch = K >> 6;
    load_chunk(sb, tid, Ah, Al, Bh, Bl, m0, n0, 0, K);
    CP_COMMIT();
    for (int i = 0; i < nch; i++) {
        if (i + 1 < nch) {
            load_chunk(sb + ((i + 1) & 1) * 65536, tid, Ah, Al, Bh, Bl,
                       m0, n0, (i + 1) << 6, K);
            CP_COMMIT();
            CP_WAIT1();
        } else {
            CP_WAIT0();
        }
        __syncthreads();
        compute_chunk(sb + (i & 1) * 65536, wm, wn, lane, acc);
        __syncthreads();
    }

    const int gr = lane >> 2;
    const int gc = (lane & 3) * 2;
#pragma unroll
    for (int mi = 0; mi < 4; mi++) {
        int r0 = m0 + wm * 64 + mi * 16 + gr;
#pragma unroll
        for (int ni = 0; ni < 4; ni++) {
            int c = n0 + wn * 32 + ni * 8 + gc;
            size_t o0 = (size_t)r0 * N + c;
            size_t o1 = (size_t)(r0 + 8) * N + c;
            float2 v0 = make_float2(acc[mi][ni][0], acc[mi][ni][1]);
            float2 v1 = make_float2(acc[mi][ni][2], acc[mi][ni][3]);
            if (R) {
                float2 rr0 = *(const float2*)(R + o0);
                float2 rr1 = *(const float2*)(R + o1);
                v0.x += rr0.x; v0.y += rr0.y;
                v1.x += rr1.x; v1.y += rr1.y;
            }
            *(float2*)(C + o0) = v0;
            *(float2*)(C + o1) = v1;
        }
    }
}

// ===================== int8x3 GEMM machinery (k=128 chunks) =================
__device__ __forceinline__ void load_chunk_s8(
    uint32_t buf, int tid,
    const int8_t* __restrict__ Ah, const int8_t* __restrict__ Al,
    const int8_t* __restrict__ Bh, const int8_t* __restrict__ Bl,
    int m0, int n0, int k0, int K) {
#pragma unroll
    for (int t = 0; t < 16; t++) {
        int idx = tid + t * 256;
        int tile = idx >> 10;
        int w = idx & 1023;
        int r = w >> 3, c8 = w & 7;
        const int8_t* src =
            (tile == 0 ? Ah : tile == 1 ? Al : tile == 2 ? Bh : Bl);
        int row = (tile < 2 ? m0 : n0) + r;
        uint32_t dst = buf + tile * 16384 + sw128((uint32_t)(r * 128 + c8 * 16));
        cp_async16(dst, src + (size_t)row * K + k0 + c8 * 16);
    }
}

__device__ __forceinline__ void compute_chunk_s8(
    uint32_t buf, int wm, int wn, int lane,
    int32_t hh[4][4][4], int32_t xx[4][4][4]) {
    const uint32_t bAh = buf;
    const uint32_t bAl = buf + 16384;
    const uint32_t bBh = buf + 32768;
    const uint32_t bBl = buf + 49152;
#pragma unroll
    for (int ks = 0; ks < 4; ks++) {
        uint32_t bh[4][2], bl[4][2];
#pragma unroll
        for (int ni = 0; ni < 4; ni++) {
            uint32_t rowB = wn * 32 + ni * 8 + (lane & 7);
            uint32_t kb = ks * 32 + ((lane >> 3) & 1) * 16;
            uint32_t sw = sw128(rowB * 128 + kb);
            ldsm2(bh[ni], bBh + sw);
            ldsm2(bl[ni], bBl + sw);
        }
#pragma unroll
        for (int mi = 0; mi < 4; mi++) {
            uint32_t rowA = wm * 64 + mi * 16 + (lane & 15);
            uint32_t kb = ks * 32 + (lane >> 4) * 16;
            uint32_t sw = sw128(rowA * 128 + kb);
            uint32_t ah[4], al[4];
            ldsm4(ah, bAh + sw);
            ldsm4(al, bAl + sw);
#pragma unroll
            for (int ni = 0; ni < 4; ni++) {
                mma_s8(hh[mi][ni], ah, bh[ni]);
                mma_s8(xx[mi][ni], ah, bl[ni]);
                mma_s8(xx[mi][ni], al, bh[ni]);
            }
        }
    }
}

// C = dequant(A@B) ; swiglu=0: C = val (+R); swiglu=1: C = silu(val)*C in-place
__global__ __launch_bounds__(256, 1) void gemm_s8(
    const int8_t* __restrict__ Ah, const int8_t* __restrict__ Al,
    const int8_t* __restrict__ Bh, const int8_t* __restrict__ Bl,
    const float* __restrict__ sArow, const float* __restrict__ sBcol,
    const float* __restrict__ R, float* __restrict__ C,
    int N, int K, int swiglu) {
    extern __shared__ char smem[];
    const uint32_t sb = smem_to_u32(smem);
    const int tid = threadIdx.x;
    const int wid = tid >> 5;
    const int lane = tid & 31;
    const int wm = wid & 1;
    const int wn = wid >> 1;
    const int m0 = blockIdx.x * 128;
    const int n0 = blockIdx.y * 128;

    int32_t hh[4][4][4], xx[4][4][4];
#pragma unroll
    for (int i = 0; i < 4; i++)
#pragma unroll
        for (int j = 0; j < 4; j++)
#pragma unroll
            for (int k = 0; k < 4; k++) { hh[i][j][k] = 0; xx[i][j][k] = 0; }

    const int nch = K >> 7;
    load_chunk_s8(sb, tid, Ah, Al, Bh, Bl, m0, n0, 0, K);
    CP_COMMIT();
    for (int i = 0; i < nch; i++) {
        if (i + 1 < nch) {
            load_chunk_s8(sb + ((i + 1) & 1) * 65536, tid, Ah, Al, Bh, Bl,
                          m0, n0, (i + 1) << 7, K);
            CP_COMMIT();
            CP_WAIT1();
        } else {
            CP_WAIT0();
        }
        __syncthreads();
        compute_chunk_s8(sb + (i & 1) * 65536, wm, wn, lane, hh, xx);
        __syncthreads();
    }

    const int gr = lane >> 2;
    const int gc = (lane & 3) * 2;
    const float k1 = 1.f / 254.f;
    const float k2 = 1.f / 16129.f;
#pragma unroll
    for (int mi = 0; mi < 4; mi++) {
        int r0 = m0 + wm * 64 + mi * 16 + gr;
        float sa0 = sArow[r0] * k2;
        float sa1 = sArow[r0 + 8] * k2;
#pragma unroll
        for (int ni = 0; ni < 4; ni++) {
            int c = n0 + wn * 32 + ni * 8 + gc;
            float sb0 = sBcol[c], sb1 = sBcol[c + 1];
            size_t o0 = (size_t)r0 * N + c;
            size_t o1 = (size_t)(r0 + 8) * N + c;
            float v00 = sa0 * sb0 * ((float)hh[mi][ni][0] + (float)xx[mi][ni][0] * k1);
            float v01 = sa0 * sb1 * ((float)hh[mi][ni][1] + (float)xx[mi][ni][1] * k1);
            float v10 = sa1 * sb0 * ((float)hh[mi][ni][2] + (float)xx[mi][ni][2] * k1);
            float v11 = sa1 * sb1 * ((float)hh[mi][ni][3] + (float)xx[mi][ni][3] * k1);
            if (swiglu) {
                float2 u0 = *(const float2*)(C + o0);
                float2 u1 = *(const float2*)(C + o1);
                v00 = (v00 / (1.f + expf(-v00))) * u0.x;
                v01 = (v01 / (1.f + expf(-v01))) * u0.y;
                v10 = (v10 / (1.f + expf(-v10))) * u1.x;
                v11 = (v11 / (1.f + expf(-v11))) * u1.y;
            } else if (R) {
                float2 rr0 = *(const float2*)(R + o0);
                float2 rr1 = *(const float2*)(R + o1);
                v00 += rr0.x; v01 += rr0.y;
                v10 += rr1.x; v11 += rr1.y;
            }
            *(float2*)(C + o0) = make_float2(v00, v01);
            *(float2*)(C + o1) = make_float2(v10, v11);
        }
    }
}

// ===================== attention QK^T =======================================
__global__ __launch_bounds__(256, 1) void attn_qk(
    const __nv_bfloat16* __restrict__ Qh, const __nv_bfloat16* __restrict__ Ql,
    const __nv_bfloat16* __restrict__ Kh, const __nv_bfloat16* __restrict__ Kl,
    const int* __restrict__ cu, int nseg, float* __restrict__ scores) {
    extern __shared__ char smem[];
    const uint32_t sb = smem_to_u32(smem);
    const int h = blockIdx.z / nseg, s = blockIdx.z % nseg;
    const int s0 = cu[s];
    const int L = cu[s + 1] - s0;
    const int q0 = blockIdx.y * 128, kt0 = blockIdx.x * 128;
    if (q0 >= L || kt0 >= L) return;
    const int tid = threadIdx.x;
    const int wid = tid >> 5, lane = tid & 31;
    const int wm = wid & 1, wn = wid >> 1;

    const __nv_bfloat16* qh = Qh + ((size_t)h * SEQ + s0 + q0) * HD;
    const __nv_bfloat16* ql = Ql + ((size_t)h * SEQ + s0 + q0) * HD;
    const __nv_bfloat16* kh = Kh + ((size_t)h * SEQ + s0 + kt0) * HD;
    const __nv_bfloat16* kl = Kl + ((size_t)h * SEQ + s0 + kt0) * HD;

    float acc[4][4][4];
#pragma unroll
    for (int i = 0; i < 4; i++)
#pragma unroll
        for (int j = 0; j < 4; j++)
#pragma unroll
            for (int k = 0; k < 4; k++) acc[i][j][k] = 0.f;

    load_chunk(sb, tid, qh, ql, kh, kl, 0, 0, 0, HD);
    CP_COMMIT();
    for (int i = 0; i < 2; i++) {
        if (i == 0) {
            load_chunk(sb + 65536, tid, qh, ql, kh, kl, 0, 0, 64, HD);
            CP_COMMIT();
            CP_WAIT1();
        } else {
            CP_WAIT0();
        }
        __syncthreads();
        compute_chunk(sb + i * 65536, wm, wn, lane, acc);
        __syncthreads();
    }

    const float scale = 0.088388347648318447f;
    const int gr = lane >> 2;
    const int gc = (lane & 3) * 2;
#pragma unroll
    for (int mi = 0; mi < 4; mi++) {
        int qg = s0 + q0 + wm * 64 + mi * 16 + gr;
#pragma unroll
        for (int ni = 0; ni < 4; ni++) {
            int c = kt0 + wn * 32 + ni * 8 + gc;
            size_t o0 = ((size_t)h * SEQ + qg) * MAXL + c;
            size_t o1 = ((size_t)h * SEQ + qg + 8) * MAXL + c;
            *(float2*)(scores + o0) =
                make_float2(acc[mi][ni][0] * scale, acc[mi][ni][1] * scale);
            *(float2*)(scores + o1) =
                make_float2(acc[mi][ni][2] * scale, acc[mi][ni][3] * scale);
        }
    }
}

// ===================== softmax -> P hi/lo bf16 ==============================
__global__ void softmax_psplit(float* __restrict__ scores,
                               const int* __restrict__ cu, int nseg,
                               __nv_bfloat16* __restrict__ ph,
                               __nv_bfloat16* __restrict__ pl) {
    int row = blockIdx.x;
    int q = row % SEQ;
    int L = MAXL;
    for (int s = 0; s < nseg; s++)
        if (q >= cu[s] && q < cu[s + 1]) { L = cu[s + 1] - cu[s]; break; }
    float* r = scores + (size_t)row * MAXL;
    int tid = threadIdx.x;
    __shared__ float red[256];
    float m = -3.4e38f;
    for (int i = tid; i < L; i += 256) m = fmaxf(m, r[i]);
    red[tid] = m;
    __syncthreads();
    for (int s = 128; s > 0; s >>= 1) {
        if (tid < s) red[tid] = fmaxf(red[tid], red[tid + s]);
        __syncthreads();
    }
    m = red[0];
    __syncthreads();
    float sum = 0.f;
    for (int i = tid; i < L; i += 256) {
        float e = expf(r[i] - m);
        r[i] = e;
        sum += e;
    }
    red[tid] = sum;
    __syncthreads();
    for (int s = 128; s > 0; s >>= 1) {
        if (tid < s) red[tid] += red[tid + s];
        __syncthreads();
    }
    float inv = 1.f / red[0];
    for (int i = tid; i < L; i += 256) {
        float p = r[i] * inv;
        __nv_bfloat16 hh, ll;
        split_bf16(p, hh, ll);
        ph[(size_t)row * MAXL + i] = hh;
        pl[(size_t)row * MAXL + i] = ll;
    }
}

// ===================== attention P@V ========================================
__device__ __forceinline__ void load_chunk_pv(
    uint32_t buf, int tid,
    const __nv_bfloat16* __restrict__ Ph, const __nv_bfloat16* __restrict__ Pl,
    const __nv_bfloat16* __restrict__ Vh, const __nv_bfloat16* __restrict__ Vl,
    int k0) {
#pragma unroll
    for (int t = 0; t < 16; t++) {
        int idx = tid + t * 256;
        int tile = idx >> 10;
        int w = idx & 1023;
        if (tile < 2) {
            int r = w >> 3, c8 = w & 7;
            const __nv_bfloat16* src = (tile == 0) ? Ph : Pl;
            uint32_t dst = buf + tile * 16384 + sw128((uint32_t)(r * 128 + c8 * 16));
            cp_async16(dst, src + (size_t)r * MAXL + k0 + c8 * 8);
        } else {
            int r = w >> 4, c = w & 15;
            const __nv_bfloat16* src = (tile == 2) ? Vh : Vl;
            uint32_t dst = buf + 32768 + (tile - 2) * 16384 +
                           sw128((uint32_t)(r * 256 + c * 16));
            cp_async16(dst, src + (size_t)(k0 + r) * HD + c * 8);
        }
    }
}

__global__ __launch_bounds__(256, 1) void attn_pv_mma(
    const __nv_bfloat16* __restrict__ Ph, const __nv_bfloat16* __restrict__ Pl,
    const __nv_bfloat16* __restrict__ Vh, const __nv_bfloat16* __restrict__ Vl,
    const int* __restrict__ cu, int nseg,
    __nv_bfloat16* __restrict__ oh, __nv_bfloat16* __restrict__ ol) {
    extern __shared__ char smem[];
    const uint32_t sb = smem_to_u32(smem);
    const int h = blockIdx.z / nseg, s = blockIdx.z % nseg;
    const int s0 = cu[s];
    const int L = cu[s + 1] - s0;
    const int q0 = blockIdx.y * 128;
    if (q0 >= L) return;
    const int tid = threadIdx.x;
    const int wid = tid >> 5, lane = tid & 31;
    const int wm = wid & 1, wn = wid >> 1;

    const __nv_bfloat16* ph = Ph + ((size_t)h * SEQ + s0 + q0) * MAXL;
    const __nv_bfloat16* pl = Pl + ((size_t)h * SEQ + s0 + q0) * MAXL;
    const __nv_bfloat16* vh = Vh + ((size_t)h * SEQ + s0) * HD;
    const __nv_bfloat16* vl = Vl + ((size_t)h * SEQ + s0) * HD;

    float acc[4][4][4];
#pragma unroll
    for (int i = 0; i < 4; i++)
#pragma unroll
        for (int j = 0; j < 4; j++)
#pragma unroll
            for (int k = 0; k < 4; k++) acc[i][j][k] = 0.f;

    const int nch = L >> 6;
    load_chunk_pv(sb, tid, ph, pl, vh, vl, 0);
    CP_COMMIT();
    for (int i = 0; i < nch; i++) {
        if (i + 1 < nch) {
            load_chunk_pv(sb + ((i + 1) & 1) * 65536, tid, ph, pl, vh, vl, (i + 1) << 6);
            CP_COMMIT();
            CP_WAIT1();
        } else {
            CP_WAIT0();
        }
        __syncthreads();
        {
            const uint32_t buf = sb + (i & 1) * 65536;
            const uint32_t bAh = buf;
            const uint32_t bAl = buf + 16384;
            const uint32_t bBh = buf + 32768;
            const uint32_t bBl = buf + 49152;
#pragma unroll
            for (int ks = 0; ks < 4; ks++) {
                uint32_t bh[4][2], bl[4][2];
#pragma unroll
                for (int ni = 0; ni < 4; ni++) {
                    uint32_t nb = (wn * 32 + ni * 8) * 2;
                    uint32_t sw = sw128((ks * 16 + (lane & 15)) * 256 + nb);
                    ldsm2t(bh[ni], bBh + sw);
                    ldsm2t(bl[ni], bBl + sw);
                }
#pragma unroll
                for (int mi = 0; mi < 4; mi++) {
                    uint32_t rowA = wm * 64 + mi * 16 + (lane & 15);
                    uint32_t kb = ks * 32 + (lane >> 4) * 16;
                    uint32_t sw = sw128(rowA * 128 + kb);
                    uint32_t ah[4], al[4];
                    ldsm4(ah, bAh + sw);
                    ldsm4(al, bAl + sw);
#pragma unroll
                    for (int ni = 0; ni < 4; ni++) {
                        mma_bf16(acc[mi][ni], ah, bh[ni]);
                        mma_bf16(acc[mi][ni], ah, bl[ni]);
                        mma_bf16(acc[mi][ni], al, bh[ni]);
                    }
                }
            }
        }
        __syncthreads();
    }

    const int gr = lane >> 2;
    const int gc = (lane & 3) * 2;
#pragma unroll
    for (int mi = 0; mi < 4; mi++) {
        int qg = s0 + q0 + wm * 64 + mi * 16 + gr;
#pragma unroll
        for (int ni = 0; ni < 4; ni++) {
            int d = wn * 32 + ni * 8 + gc;
            size_t o0 = (size_t)qg * HID + h * HD + d;
            size_t o1 = (size_t)(qg + 8) * HID + h * HD + d;
            __nv_bfloat16 hh, ll;
            split_bf16(acc[mi][ni][0], hh, ll); oh[o0] = hh; ol[o0] = ll;
            split_bf16(acc[mi][ni][1], hh, ll); oh[o0 + 1] = hh; ol[o0 + 1] = ll;
            split_bf16(acc[mi][ni][2], hh, ll); oh[o1] = hh; ol[o1] = ll;
            split_bf16(acc[mi][ni][3], hh, ll); oh[o1 + 1] = hh; ol[o1 + 1] = ll;
        }
    }
}

// ===================== RMSNorm -> bf16 hi/lo (norm1) ========================
__global__ void rmsnorm_split(const float* __restrict__ x, const float* __restrict__ w,
                              __nv_bfloat16* __restrict__ yh, __nv_bfloat16* __restrict__ yl) {
    int row = blockIdx.x;
    const float* xr = x + (size_t)row * HID;
    int tid = threadIdx.x;
    float ss = 0.f;
    for (int i = tid; i < HID; i += 256) { float v = xr[i]; ss += v * v; }
    __shared__ float red[256];
    red[tid] = ss;
    __syncthreads();
    for (int s = 128; s > 0; s >>= 1) {
        if (tid < s) red[tid] += red[tid + s];
        __syncthreads();
    }
    float inv = rsqrtf(red[0] / (float)HID + EPS);
    for (int i = tid; i < HID; i += 256) {
        float v = xr[i] * inv * w[i];
        __nv_bfloat16 h, l;
        split_bf16(v, h, l);
        yh[(size_t)row * HID + i] = h;
        yl[(size_t)row * HID + i] = l;
    }
}

// ===================== RMSNorm -> int8 hi/lo + row scale (norm2) ============
__global__ void rmsnorm_q8(const float* __restrict__ x, const float* __restrict__ w,
                           int8_t* __restrict__ yh, int8_t* __restrict__ yl,
                           float* __restrict__ srow) {
    int row = blockIdx.x;
    const float* xr = x + (size_t)row * HID;
    int tid = threadIdx.x;
    __shared__ float vbuf[HID];
    __shared__ float red[256];
    float ss = 0.f;
    for (int i = tid; i < HID; i += 256) { float v = xr[i]; ss += v * v; }
    red[tid] = ss;
    __syncthreads();
    for (int s = 128; s > 0; s >>= 1) {
        if (tid < s) red[tid] += red[tid + s];
        __syncthreads();
    }
    float inv = rsqrtf(red[0] / (float)HID + EPS);
    __syncthreads();
    float mx = 0.f;
    for (int i = tid; i < HID; i += 256) {
        float v = xr[i] * inv * w[i];
        vbuf[i] = v;
        mx = fmaxf(mx, fabsf(v));
    }
    red[tid] = mx;
    __syncthreads();
    for (int s = 128; s > 0; s >>= 1) {
        if (tid < s) red[tid] = fmaxf(red[tid], red[tid + s]);
        __syncthreads();
    }
    float sc = fmaxf(red[0], 1e-30f);
    if (tid == 0) srow[row] = sc;
    float q = 127.f / sc;
    for (int i = tid; i < HID; i += 256) {
        int8_t h8, l8;
        quant8(vbuf[i], q, h8, l8);
        yh[(size_t)row * HID + i] = h8;
        yl[(size_t)row * HID + i] = l8;
    }
}

// ===================== act (fp32) -> int8 hi/lo + row scale =================
__global__ void act_quant(const float* __restrict__ a,
                          int8_t* __restrict__ yh, int8_t* __restrict__ yl,
                          float* __restrict__ srow) {
    int row = blockIdx.x;
    const float* ar = a + (size_t)row * INTER;
    int tid = threadIdx.x;
    __shared__ float red[256];
    float mx = 0.f;
    for (int i = tid; i < INTER; i += 256) mx = fmaxf(mx, fabsf(ar[i]));
    red[tid] = mx;
    __syncthreads();
    for (int s = 128; s > 0; s >>= 1) {
        if (tid < s) red[tid] = fmaxf(red[tid], red[tid + s]);
        __syncthreads();
    }
    float sc = fmaxf(red[0], 1e-30f);
    if (tid == 0) srow[row] = sc;
    float q = 127.f / sc;
    for (int i = tid; i < INTER; i += 256) {
        int8_t h8, l8;
        quant8(ar[i], q, h8, l8);
        yh[(size_t)row * INTER + i] = h8;
        yl[(size_t)row * INTER + i] = l8;
    }
}

// ===================== RoPE + per-head split ================================
__global__ void rope_split(const float* __restrict__ qkv, const float* __restrict__ rot,
                           __nv_bfloat16* __restrict__ qh, __nv_bfloat16* __restrict__ ql,
                           __nv_bfloat16* __restrict__ kh, __nv_bfloat16* __restrict__ kl,
                           __nv_bfloat16* __restrict__ vh, __nv_bfloat16* __restrict__ vl) {
    int n = blockIdx.x, h = blockIdx.y, d = threadIdx.x;
    float ang = rot[n * HD + d];
    float c = cosf(ang), s = sinf(ang);
    const float* q = qkv + (size_t)n * QKVW + h * HD;
    const float* k = q + HID;
    const float* v = q + 2 * HID;
    int p = (d < 64) ? d + 64 : d - 64;
    float sgn = (d < 64) ? -1.f : 1.f;
    float qr = q[d] * c + sgn * q[p] * s;
    float kr = k[d] * c + sgn * k[p] * s;
    float vv = v[d];
    size_t o = ((size_t)h * SEQ + n) * HD + d;
    __nv_bfloat16 hh, ll;
    split_bf16(qr, hh, ll); qh[o] = hh; ql[o] = ll;
    split_bf16(kr, hh, ll); kh[o] = hh; kl[o] = ll;
    split_bf16(vv, hh, ll); vh[o] = hh; vl[o] = ll;
}

// ===================== host orchestration ===================================
extern "C" void kernel_launch(void* const* d_in, const int* in_sizes, int n_in,
                              void* d_out, int out_size) {
    const float* hidden = (const float*)d_in[0];
    const float* rot    = (const float*)d_in[1];
    const float* n1w    = (const float*)d_in[2];
    const float* n2w    = (const float*)d_in[3];
    const float* qkv_w  = (const float*)d_in[4];
    const float* proj_w = (const float*)d_in[5];
    const float* gate_w = (const float*)d_in[6];
    const float* up_w   = (const float*)d_in[7];
    const float* down_w = (const float*)d_in[8];
    const int*   cu     = (const int*)d_in[9];
    float* out = (float*)d_out;
    int nseg = in_sizes[9] - 1;

    const int GEMM_SMEM = 2 * 65536;
    cudaFuncSetAttribute(gemm_bf16x3, cudaFuncAttributeMaxDynamicSharedMemorySize, GEMM_SMEM);
    cudaFuncSetAttribute(gemm_s8, cudaFuncAttributeMaxDynamicSharedMemorySize, GEMM_SMEM);
    cudaFuncSetAttribute(attn_qk, cudaFuncAttributeMaxDynamicSharedMemorySize, GEMM_SMEM);
    cudaFuncSetAttribute(attn_pv_mma, cudaFuncAttributeMaxDynamicSharedMemorySize, GEMM_SMEM);

    float *p_qkv, *p_scores, *p_hid2, *p_up;
    cudaGetSymbolAddress((void**)&p_qkv,    g_qkv);
    cudaGetSymbolAddress((void**)&p_scores, g_scores);
    cudaGetSymbolAddress((void**)&p_hid2,   g_hid2);
    cudaGetSymbolAddress((void**)&p_up,     g_up);
    __nv_bfloat16 *hn_h, *hn_l, *at_h, *at_l;
    __nv_bfloat16 *q_h, *q_l, *k_h, *k_l, *v_h, *v_l, *pp_h, *pp_l;
    __nv_bfloat16 *wq_h, *wq_l, *wp_h, *wp_l;
    cudaGetSymbolAddress((void**)&hn_h, g_hn_h);   cudaGetSymbolAddress((void**)&hn_l, g_hn_l);
    cudaGetSymbolAddress((void**)&at_h, g_at_h);   cudaGetSymbolAddress((void**)&at_l, g_at_l);
    cudaGetSymbolAddress((void**)&q_h, g_q_h);     cudaGetSymbolAddress((void**)&q_l, g_q_l);
    cudaGetSymbolAddress((void**)&k_h, g_k_h);     cudaGetSymbolAddress((void**)&k_l, g_k_l);
    cudaGetSymbolAddress((void**)&v_h, g_v_h);     cudaGetSymbolAddress((void**)&v_l, g_v_l);
    cudaGetSymbolAddress((void**)&pp_h, g_p_h);    cudaGetSymbolAddress((void**)&pp_l, g_p_l);
    cudaGetSymbolAddress((void**)&wq_h, g_wqkv_h); cudaGetSymbolAddress((void**)&wq_l, g_wqkv_l);
    cudaGetSymbolAddress((void**)&wp_h, g_wproj_h);cudaGetSymbolAddress((void**)&wp_l, g_wproj_l);

    int8_t *a8h, *a8l, *act8h, *act8l, *wg8h, *wg8l, *wu8h, *wu8l, *wd8h, *wd8l;
    float *sa, *sact, *sg, *su, *sd;
    cudaGetSymbolAddress((void**)&a8h, g_a8h);     cudaGetSymbolAddress((void**)&a8l, g_a8l);
    cudaGetSymbolAddress((void**)&act8h, g_act8h); cudaGetSymbolAddress((void**)&act8l, g_act8l);
    cudaGetSymbolAddress((void**)&wg8h, g_wg8h);   cudaGetSymbolAddress((void**)&wg8l, g_wg8l);
    cudaGetSymbolAddress((void**)&wu8h, g_wu8h);   cudaGetSymbolAddress((void**)&wu8l, g_wu8l);
    cudaGetSymbolAddress((void**)&wd8h, g_wd8h);   cudaGetSymbolAddress((void**)&wd8l, g_wd8l);
    cudaGetSymbolAddress((void**)&sa, g_sa);       cudaGetSymbolAddress((void**)&sact, g_sact);
    cudaGetSymbolAddress((void**)&sg, g_sg);       cudaGetSymbolAddress((void**)&su, g_su);
    cudaGetSymbolAddress((void**)&sd, g_sd);

    dim3 tb(32, 8);
    // bf16 weights (qkv, proj)
    wconv_t<<<dim3(QKVW / 32, HID / 32), tb>>>(qkv_w, wq_h, wq_l, HID, QKVW);
    wconv_t<<<dim3(HID / 32, HID / 32), tb>>>(proj_w, wp_h, wp_l, HID, HID);
    // int8 weights (gate, up, down)
    wconv_q8<<<INTER / 32, tb>>>(gate_w, wg8h, wg8l, sg, HID, INTER);
    wconv_q8<<<INTER / 32, tb>>>(up_w, wu8h, wu8l, su, HID, INTER);
    wconv_q8<<<HID / 32, tb>>>(down_w, wd8h, wd8l, sd, INTER, HID);

    // 1. norm1 (bf16)
    rmsnorm_split<<<SEQ, 256>>>(hidden, n1w, hn_h, hn_l);
    // 2. qkv (bf16x3)
    gemm_bf16x3<<<dim3(SEQ / 128, QKVW / 128), 256, GEMM_SMEM>>>(
        hn_h, hn_l, wq_h, wq_l, nullptr, p_qkv, QKVW, HID);
    // 3. rope + per-head bf16 split
    rope_split<<<dim3(SEQ, NH), HD>>>(p_qkv, rot, q_h, q_l, k_h, k_l, v_h, v_l);
    // 4. scores
    attn_qk<<<dim3(MAXL / 128, MAXL / 128, NH * nseg), 256, GEMM_SMEM>>>(
        q_h, q_l, k_h, k_l, cu, nseg, p_scores);
    // 5. softmax -> P hi/lo
    softmax_psplit<<<NH * SEQ, 256>>>(p_scores, cu, nseg, pp_h, pp_l);
    // 6. O = P @ V
    attn_pv_mma<<<dim3(1, MAXL / 128, NH * nseg), 256, GEMM_SMEM>>>(
        pp_h, pp_l, v_h, v_l, cu, nseg, at_h, at_l);
    // 7. hid2 = attn @ proj_w + hidden (bf16x3)
    gemm_bf16x3<<<dim3(SEQ / 128, HID / 128), 256, GEMM_SMEM>>>(
        at_h, at_l, wp_h, wp_l, hidden, p_hid2, HID, HID);
    // 8. norm2 -> int8 + row scale
    rmsnorm_q8<<<SEQ, 256>>>(p_hid2, n2w, a8h, a8l, sa);
    // 9. up = h2n @ up_w (int8x3, fp32 out)
    gemm_s8<<<dim3(SEQ / 128, INTER / 128), 256, GEMM_SMEM>>>(
        a8h, a8l, wu8h, wu8l, sa, su, nullptr, p_up, INTER, HID, 0);
    // 10. gate + swiglu in-place: p_up <- silu(gate)*up
    gemm_s8<<<dim3(SEQ / 128, INTER / 128), 256, GEMM_SMEM>>>(
        a8h, a8l, wg8h, wg8l, sa, sg, nullptr, p_up, INTER, HID, 1);
    // 11. act -> int8 + row scale
    act_quant<<<SEQ, 256>>>(p_up, act8h, act8l, sact);
    // 12. out = act @ down_w + hid2 (int8x3)
    gemm_s8<<<dim3(SEQ / 128, HID / 128), 256, GEMM_SMEM>>>(
        act8h, act8l, wd8h, wd8l, sact, sd, p_hid2, out, HID, INTER, 0);
}

// round 12
// speedup vs baseline: 2.6797x; 2.6797x over previous
#include <cuda_runtime.h>
#include <cuda_bf16.h>
#include <cstdint>
#include <math.h>

#define SEQ    3072
#define HID    1536
#define NH     12
#define HD     128
#define QKVW   4608   // 3*HID
#define INTER  13696
#define MAXL   1024
#define EPS    1e-6f

// ===================== PTX helpers (baseline PTX only) ======================
__device__ __forceinline__ uint32_t smem_to_u32(const void* p) {
    uint32_t a;
    asm("{ .reg .u64 t; cvta.to.shared.u64 t, %1; cvt.u32.u64 %0, t; }"
        : "=r"(a) : "l"(p));
    return a;
}
__device__ __forceinline__ void cp_async16(uint32_t dst, const void* src) {
    asm volatile("cp.async.cg.shared.global [%0], [%1], 16;"
                 :: "r"(dst), "l"(src) : "memory");
}
#define CP_COMMIT() asm volatile("cp.async.commit_group;" ::: "memory")
#define CP_WAIT1()  asm volatile("cp.async.wait_group 1;" ::: "memory")
#define CP_WAIT0()  asm volatile("cp.async.wait_group 0;" ::: "memory")

__device__ __forceinline__ void ldsm4(uint32_t* r, uint32_t addr) {
    asm volatile("ldmatrix.sync.aligned.m8n8.x4.shared.b16 {%0,%1,%2,%3}, [%4];"
                 : "=r"(r[0]), "=r"(r[1]), "=r"(r[2]), "=r"(r[3]) : "r"(addr));
}
__device__ __forceinline__ void ldsm2(uint32_t* r, uint32_t addr) {
    asm volatile("ldmatrix.sync.aligned.m8n8.x2.shared.b16 {%0,%1}, [%2];"
                 : "=r"(r[0]), "=r"(r[1]) : "r"(addr));
}
__device__ __forceinline__ void ldsm2t(uint32_t* r, uint32_t addr) {
    asm volatile("ldmatrix.sync.aligned.m8n8.x2.trans.shared.b16 {%0,%1}, [%2];"
                 : "=r"(r[0]), "=r"(r[1]) : "r"(addr));
}
__device__ __forceinline__ void mma_bf16(float* c, const uint32_t* a, const uint32_t* b) {
    asm volatile("mma.sync.aligned.m16n8k16.row.col.f32.bf16.bf16.f32 "
                 "{%0,%1,%2,%3}, {%4,%5,%6,%7}, {%8,%9}, {%0,%1,%2,%3};"
                 : "+f"(c[0]), "+f"(c[1]), "+f"(c[2]), "+f"(c[3])
                 : "r"(a[0]), "r"(a[1]), "r"(a[2]), "r"(a[3]),
                   "r"(b[0]), "r"(b[1]));
}
__device__ __forceinline__ void split_bf16(float v, __nv_bfloat16& h, __nv_bfloat16& l) {
    h = __float2bfloat16(v);
    l = __float2bfloat16(v - __bfloat162float(h));
}
__device__ __forceinline__ uint32_t sw128(uint32_t off) {
    return off ^ ((off >> 3) & 0x70);
}

// ===================== scratch =============================================
__device__ float g_qkv   [SEQ * QKVW];
__device__ float g_scores[(size_t)NH * SEQ * MAXL];
__device__ float g_hid2  [SEQ * HID];

__device__ __nv_bfloat16 g_hn_h [SEQ * HID],  g_hn_l [SEQ * HID];
__device__ __nv_bfloat16 g_h2n_h[SEQ * HID],  g_h2n_l[SEQ * HID];
__device__ __nv_bfloat16 g_at_h [SEQ * HID],  g_at_l [SEQ * HID];
__device__ __nv_bfloat16 g_act_h[(size_t)SEQ * INTER], g_act_l[(size_t)SEQ * INTER];

__device__ __nv_bfloat16 g_q_h[(size_t)NH * SEQ * HD], g_q_l[(size_t)NH * SEQ * HD];
__device__ __nv_bfloat16 g_k_h[(size_t)NH * SEQ * HD], g_k_l[(size_t)NH * SEQ * HD];
__device__ __nv_bfloat16 g_v_h[(size_t)NH * SEQ * HD], g_v_l[(size_t)NH * SEQ * HD];
__device__ __nv_bfloat16 g_p_h[(size_t)NH * SEQ * MAXL], g_p_l[(size_t)NH * SEQ * MAXL];

__device__ __nv_bfloat16 g_wqkv_h [(size_t)QKVW * HID],  g_wqkv_l [(size_t)QKVW * HID];
__device__ __nv_bfloat16 g_wproj_h[(size_t)HID * HID],   g_wproj_l[(size_t)HID * HID];
__device__ __nv_bfloat16 g_wgate_h[(size_t)INTER * HID], g_wgate_l[(size_t)INTER * HID];
__device__ __nv_bfloat16 g_wup_h  [(size_t)INTER * HID], g_wup_l  [(size_t)INTER * HID];
__device__ __nv_bfloat16 g_wdown_h[(size_t)HID * INTER], g_wdown_l[(size_t)HID * INTER];

// ===================== weight transpose + split =============================
__global__ void wconv_t(const float* __restrict__ W, __nv_bfloat16* __restrict__ Th,
                        __nv_bfloat16* __restrict__ Tl, int K, int N) {
    __shared__ float ts[32][33];
    int n0 = blockIdx.x * 32, k0 = blockIdx.y * 32;
    int tx = threadIdx.x, ty = threadIdx.y;   // 32 x 8
#pragma unroll
    for (int r = 0; r < 32; r += 8)
        ts[ty + r][tx] = W[(size_t)(k0 + ty + r) * N + n0 + tx];
    __syncthreads();
#pragma unroll
    for (int r = 0; r < 32; r += 8) {
        float v = ts[tx][ty + r];
        __nv_bfloat16 h, l;
        split_bf16(v, h, l);
        size_t o = (size_t)(n0 + ty + r) * K + k0 + tx;
        Th[o] = h;
        Tl[o] = l;
    }
}

// ===================== 128-tile GEMM machinery (attention) ==================
__device__ __forceinline__ void load_chunk(
    uint32_t buf, int tid,
    const __nv_bfloat16* __restrict__ Ah, const __nv_bfloat16* __restrict__ Al,
    const __nv_bfloat16* __restrict__ Bh, const __nv_bfloat16* __restrict__ Bl,
    int m0, int n0, int k0, int K) {
#pragma unroll
    for (int t = 0; t < 16; t++) {
        int idx = tid + t * 256;
        int tile = idx >> 10;
        int w = idx & 1023;
        int r = w >> 3, c8 = w & 7;
        const __nv_bfloat16* src =
            (tile == 0 ? Ah : tile == 1 ? Al : tile == 2 ? Bh : Bl);
        int row = (tile < 2 ? m0 : n0) + r;
        uint32_t dst = buf + tile * 16384 + sw128((uint32_t)(r * 128 + c8 * 16));
        cp_async16(dst, src + (size_t)row * K + k0 + c8 * 8);
    }
}

__device__ __forceinline__ void compute_chunk(
    uint32_t buf, int wm, int wn, int lane, float acc[4][4][4]) {
    const uint32_t bAh = buf;
    const uint32_t bAl = buf + 16384;
    const uint32_t bBh = buf + 32768;
    const uint32_t bBl = buf + 49152;
#pragma unroll
    for (int ks = 0; ks < 4; ks++) {
        uint32_t bh[4][2], bl[4][2];
#pragma unroll
        for (int ni = 0; ni < 4; ni++) {
            uint32_t rowB = wn * 32 + ni * 8 + (lane & 7);
            uint32_t kb = ks * 32 + ((lane >> 3) & 1) * 16;
            uint32_t sw = sw128(rowB * 128 + kb);
            ldsm2(bh[ni], bBh + sw);
            ldsm2(bl[ni], bBl + sw);
        }
#pragma unroll
        for (int mi = 0; mi < 4; mi++) {
            uint32_t rowA = wm * 64 + mi * 16 + (lane & 15);
            uint32_t kb = ks * 32 + (lane >> 4) * 16;
            uint32_t sw = sw128(rowA * 128 + kb);
            uint32_t ah[4], al[4];
            ldsm4(ah, bAh + sw);
            ldsm4(al, bAl + sw);
#pragma unroll
            for (int ni = 0; ni < 4; ni++) {
                mma_bf16(acc[mi][ni], ah, bh[ni]);
                mma_bf16(acc[mi][ni], ah, bl[ni]);
                mma_bf16(acc[mi][ni], al, bh[ni]);
            }
        }
    }
}

// ===================== 256x128 GEMM (qkv / proj / down) =====================
// stage: Ah 32K@0, Al 32K@32K, Bh 16K@64K, Bl 16K@80K = 96KB; 2 stages = 192KB
#define STG256 98304
__device__ __forceinline__ void load_chunk256(
    uint32_t buf, int tid,
    const __nv_bfloat16* __restrict__ Ah, const __nv_bfloat16* __restrict__ Al,
    const __nv_bfloat16* __restrict__ Bh, const __nv_bfloat16* __restrict__ Bl,
    int m0, int n0, int k0, int K) {
#pragma unroll
    for (int t = 0; t < 24; t++) {
        int idx = tid + t * 256;            // 0..6143 16B-units
        if (idx < 4096) {                   // A: 256 rows x 8 units, hi/lo
            const __nv_bfloat16* src = (idx < 2048) ? Ah : Al;
            int u = idx & 2047;
            int r = u >> 3, c8 = u & 7;
            uint32_t dst = buf + (idx < 2048 ? 0 : 32768)
                         + sw128((uint32_t)(r * 128 + c8 * 16));
            cp_async16(dst, src + (size_t)(m0 + r) * K + k0 + c8 * 8);
        } else {                            // B: 128 rows x 8 units, hi/lo
            int v = idx - 4096;
            const __nv_bfloat16* src = (v < 1024) ? Bh : Bl;
            int u = v & 1023;
            int r = u >> 3, c8 = u & 7;
            uint32_t dst = buf + 65536 + (v < 1024 ? 0 : 16384)
                         + sw128((uint32_t)(r * 128 + c8 * 16));
            cp_async16(dst, src + (size_t)(n0 + r) * K + k0 + c8 * 8);
        }
    }
}

__global__ __launch_bounds__(256, 1) void gemm_bf16x3_256(
    const __nv_bfloat16* __restrict__ Ah, const __nv_bfloat16* __restrict__ Al,
    const __nv_bfloat16* __restrict__ Bh, const __nv_bfloat16* __restrict__ Bl,
    const float* __restrict__ R, float* __restrict__ C, int N, int K) {
    extern __shared__ char smem[];
    const uint32_t sb = smem_to_u32(smem);
    const int tid = threadIdx.x;
    const int wid = tid >> 5;
    const int lane = tid & 31;
    const int wm = wid & 3;      // 4 x 64 rows
    const int wn = wid >> 2;     // 2 x 64 cols
    const int m0 = blockIdx.x * 256;
    const int n0 = blockIdx.y * 128;

    float acc[4][8][4];
#pragma unroll
    for (int i = 0; i < 4; i++)
#pragma unroll
        for (int j = 0; j < 8; j++)
#pragma unroll
            for (int k = 0; k < 4; k++) acc[i][j][k] = 0.f;

    const int nch = K >> 6;
    load_chunk256(sb, tid, Ah, Al, Bh, Bl, m0, n0, 0, K);
    CP_COMMIT();
    for (int i = 0; i < nch; i++) {
        if (i + 1 < nch) {
            load_chunk256(sb + ((i + 1) & 1) * STG256, tid, Ah, Al, Bh, Bl,
                          m0, n0, (i + 1) << 6, K);
            CP_COMMIT();
            CP_WAIT1();
        } else {
            CP_WAIT0();
        }
        __syncthreads();
        {
            const uint32_t buf = sb + (i & 1) * STG256;
            const uint32_t bAh = buf;
            const uint32_t bAl = buf + 32768;
            const uint32_t bBh = buf + 65536;
            const uint32_t bBl = buf + 81920;
#pragma unroll
            for (int ks = 0; ks < 4; ks++) {
                uint32_t bh[8][2], bl[8][2];
#pragma unroll
                for (int ni = 0; ni < 8; ni++) {
                    uint32_t rowB = wn * 64 + ni * 8 + (lane & 7);
                    uint32_t kb = ks * 32 + ((lane >> 3) & 1) * 16;
                    uint32_t sw = sw128(rowB * 128 + kb);
                    ldsm2(bh[ni], bBh + sw);
                    ldsm2(bl[ni], bBl + sw);
                }
#pragma unroll
                for (int mi = 0; mi < 4; mi++) {
                    uint32_t rowA = wm * 64 + mi * 16 + (lane & 15);
                    uint32_t kb = ks * 32 + (lane >> 4) * 16;
                    uint32_t sw = sw128(rowA * 128 + kb);
                    uint32_t ah[4], al[4];
                    ldsm4(ah, bAh + sw);
                    ldsm4(al, bAl + sw);
#pragma unroll
                    for (int ni = 0; ni < 8; ni++) {
                        mma_bf16(acc[mi][ni], ah, bh[ni]);
                        mma_bf16(acc[mi][ni], ah, bl[ni]);
                        mma_bf16(acc[mi][ni], al, bh[ni]);
                    }
                }
            }
        }
        __syncthreads();
    }

    const int gr = lane >> 2;
    const int gc = (lane & 3) * 2;
#pragma unroll
    for (int mi = 0; mi < 4; mi++) {
        int r0 = m0 + wm * 64 + mi * 16 + gr;
#pragma unroll
        for (int ni = 0; ni < 8; ni++) {
            int c = n0 + wn * 64 + ni * 8 + gc;
            size_t o0 = (size_t)r0 * N + c;
            size_t o1 = (size_t)(r0 + 8) * N + c;
            float2 v0 = make_float2(acc[mi][ni][0], acc[mi][ni][1]);
            float2 v1 = make_float2(acc[mi][ni][2], acc[mi][ni][3]);
            if (R) {
                float2 rr0 = *(const float2*)(R + o0);
                float2 rr1 = *(const float2*)(R + o1);
                v0.x += rr0.x; v0.y += rr0.y;
                v1.x += rr1.x; v1.y += rr1.y;
            }
            *(float2*)(C + o0) = v0;
            *(float2*)(C + o1) = v1;
        }
    }
}

// ===================== 256x64 fused gate+up+swiglu ==========================
// stage: Ah 32K@0, Al@32K, Gh 8K@64K, Gl@72K, Uh@80K, Ul@88K = 96KB; 2 stages
__device__ __forceinline__ void load_chunk_dual256(
    uint32_t buf, int tid,
    const __nv_bfloat16* __restrict__ Ah, const __nv_bfloat16* __restrict__ Al,
    const __nv_bfloat16* __restrict__ Gh, const __nv_bfloat16* __restrict__ Gl,
    const __nv_bfloat16* __restrict__ Uh, const __nv_bfloat16* __restrict__ Ul,
    int m0, int n0, int k0, int K) {
#pragma unroll
    for (int t = 0; t < 24; t++) {
        int idx = tid + t * 256;            // 0..6143
        if (idx < 4096) {                   // A: 256 rows, hi/lo
            const __nv_bfloat16* src = (idx < 2048) ? Ah : Al;
            int u = idx & 2047;
            int r = u >> 3, c8 = u & 7;
            uint32_t dst = buf + (idx < 2048 ? 0 : 32768)
                         + sw128((uint32_t)(r * 128 + c8 * 16));
            cp_async16(dst, src + (size_t)(m0 + r) * K + k0 + c8 * 8);
        } else {                            // G/U: 64 rows x 8 units, hi/lo
            int v = idx - 4096;             // 0..2047
            int which = v >> 9;             // 0:Gh 1:Gl 2:Uh 3:Ul
            const __nv_bfloat16* src =
                (which == 0 ? Gh : which == 1 ? Gl : which == 2 ? Uh : Ul);
            int u = v & 511;
            int r = u >> 3, c8 = u & 7;
            uint32_t dst = buf + 65536 + which * 8192
                         + sw128((uint32_t)(r * 128 + c8 * 16));
            cp_async16(dst, src + (size_t)(n0 + r) * K + k0 + c8 * 8);
        }
    }
}

__global__ __launch_bounds__(256, 1) void gemm_swiglu_dual256(
    const __nv_bfloat16* __restrict__ Ah, const __nv_bfloat16* __restrict__ Al,
    const __nv_bfloat16* __restrict__ Gh, const __nv_bfloat16* __restrict__ Gl,
    const __nv_bfloat16* __restrict__ Uh, const __nv_bfloat16* __restrict__ Ul,
    __nv_bfloat16* __restrict__ Oh, __nv_bfloat16* __restrict__ Ol,
    int N, int K) {
    extern __shared__ char smem[];
    const uint32_t sb = smem_to_u32(smem);
    const int tid = threadIdx.x;
    const int wid = tid >> 5;
    const int lane = tid & 31;
    const int wm = wid & 3;      // 4 x 64 rows
    const int wn = wid >> 2;     // 2 x 32 cols
    const int m0 = blockIdx.x * 256;
    const int n0 = blockIdx.y * 64;

    float ag[4][4][4], au[4][4][4];
#pragma unroll
    for (int i = 0; i < 4; i++)
#pragma unroll
        for (int j = 0; j < 4; j++)
#pragma unroll
            for (int k = 0; k < 4; k++) { ag[i][j][k] = 0.f; au[i][j][k] = 0.f; }

    const int nch = K >> 6;
    load_chunk_dual256(sb, tid, Ah, Al, Gh, Gl, Uh, Ul, m0, n0, 0, K);
    CP_COMMIT();
    for (int i = 0; i < nch; i++) {
        if (i + 1 < nch) {
            load_chunk_dual256(sb + ((i + 1) & 1) * STG256, tid,
                               Ah, Al, Gh, Gl, Uh, Ul, m0, n0, (i + 1) << 6, K);
            CP_COMMIT();
            CP_WAIT1();
        } else {
            CP_WAIT0();
        }
        __syncthreads();
        {
            const uint32_t buf = sb + (i & 1) * STG256;
            const uint32_t bAh = buf;
            const uint32_t bAl = buf + 32768;
            const uint32_t bGh = buf + 65536;
            const uint32_t bGl = buf + 73728;
            const uint32_t bUh = buf + 81920;
            const uint32_t bUl = buf + 90112;
#pragma unroll
            for (int ks = 0; ks < 4; ks++) {
                uint32_t gh[4][2], gl[4][2], uh[4][2], ul[4][2];
#pragma unroll
                for (int ni = 0; ni < 4; ni++) {
                    uint32_t rowB = wn * 32 + ni * 8 + (lane & 7);
                    uint32_t kb = ks * 32 + ((lane >> 3) & 1) * 16;
                    uint32_t sw = sw128(rowB * 128 + kb);
                    ldsm2(gh[ni], bGh + sw);
                    ldsm2(gl[ni], bGl + sw);
                    ldsm2(uh[ni], bUh + sw);
                    ldsm2(ul[ni], bUl + sw);
                }
#pragma unroll
                for (int mi = 0; mi < 4; mi++) {
                    uint32_t rowA = wm * 64 + mi * 16 + (lane & 15);
                    uint32_t kb = ks * 32 + (lane >> 4) * 16;
                    uint32_t sw = sw128(rowA * 128 + kb);
                    uint32_t ah[4], al[4];
                    ldsm4(ah, bAh + sw);
                    ldsm4(al, bAl + sw);
#pragma unroll
                    for (int ni = 0; ni < 4; ni++) {
                        mma_bf16(ag[mi][ni], ah, gh[ni]);
                        mma_bf16(ag[mi][ni], ah, gl[ni]);
                        mma_bf16(ag[mi][ni], al, gh[ni]);
                        mma_bf16(au[mi][ni], ah, uh[ni]);
                        mma_bf16(au[mi][ni], ah, ul[ni]);
                        mma_bf16(au[mi][ni], al, uh[ni]);
                    }
                }
            }
        }
        __syncthreads();
    }

    const int gr = lane >> 2;
    const int gc = (lane & 3) * 2;
#pragma unroll
    for (int mi = 0; mi < 4; mi++) {
        int r0 = m0 + wm * 64 + mi * 16 + gr;
#pragma unroll
        for (int ni = 0; ni < 4; ni++) {
            int c = n0 + wn * 32 + ni * 8 + gc;
            size_t o0 = (size_t)r0 * N + c;
            size_t o1 = (size_t)(r0 + 8) * N + c;
            float g, u, v;
            __nv_bfloat16 h, l;
            g = ag[mi][ni][0]; u = au[mi][ni][0];
            v = (g / (1.f + expf(-g))) * u;
            split_bf16(v, h, l); Oh[o0] = h; Ol[o0] = l;
            g = ag[mi][ni][1]; u = au[mi][ni][1];
            v = (g / (1.f + expf(-g))) * u;
            split_bf16(v, h, l); Oh[o0 + 1] = h; Ol[o0 + 1] = l;
            g = ag[mi][ni][2]; u = au[mi][ni][2];
            v = (g / (1.f + expf(-g))) * u;
            split_bf16(v, h, l); Oh[o1] = h; Ol[o1] = l;
            g = ag[mi][ni][3]; u = au[mi][ni][3];
            v = (g / (1.f + expf(-g))) * u;
            split_bf16(v, h, l); Oh[o1 + 1] = h; Ol[o1 + 1] = l;
        }
    }
}

// ===================== attention QK^T =======================================
__global__ __launch_bounds__(256, 1) void attn_qk(
    const __nv_bfloat16* __restrict__ Qh, const __nv_bfloat16* __restrict__ Ql,
    const __nv_bfloat16* __restrict__ Kh, const __nv_bfloat16* __restrict__ Kl,
    const int* __restrict__ cu, int nseg, float* __restrict__ scores) {
    extern __shared__ char smem[];
    const uint32_t sb = smem_to_u32(smem);
    const int h = blockIdx.z / nseg, s = blockIdx.z % nseg;
    const int s0 = cu[s];
    const int L = cu[s + 1] - s0;
    const int q0 = blockIdx.y * 128, kt0 = blockIdx.x * 128;
    if (q0 >= L || kt0 >= L) return;
    const int tid = threadIdx.x;
    const int wid = tid >> 5, lane = tid & 31;
    const int wm = wid & 1, wn = wid >> 1;

    const __nv_bfloat16* qh = Qh + ((size_t)h * SEQ + s0 + q0) * HD;
    const __nv_bfloat16* ql = Ql + ((size_t)h * SEQ + s0 + q0) * HD;
    const __nv_bfloat16* kh = Kh + ((size_t)h * SEQ + s0 + kt0) * HD;
    const __nv_bfloat16* kl = Kl + ((size_t)h * SEQ + s0 + kt0) * HD;

    float acc[4][4][4];
#pragma unroll
    for (int i = 0; i < 4; i++)
#pragma unroll
        for (int j = 0; j < 4; j++)
#pragma unroll
            for (int k = 0; k < 4; k++) acc[i][j][k] = 0.f;

    load_chunk(sb, tid, qh, ql, kh, kl, 0, 0, 0, HD);
    CP_COMMIT();
    for (int i = 0; i < 2; i++) {
        if (i == 0) {
            load_chunk(sb + 65536, tid, qh, ql, kh, kl, 0, 0, 64, HD);
            CP_COMMIT();
            CP_WAIT1();
        } else {
            CP_WAIT0();
        }
        __syncthreads();
        compute_chunk(sb + i * 65536, wm, wn, lane, acc);
        __syncthreads();
    }

    const float scale = 0.088388347648318447f;
    const int gr = lane >> 2;
    const int gc = (lane & 3) * 2;
#pragma unroll
    for (int mi = 0; mi < 4; mi++) {
        int qg = s0 + q0 + wm * 64 + mi * 16 + gr;
#pragma unroll
        for (int ni = 0; ni < 4; ni++) {
            int c = kt0 + wn * 32 + ni * 8 + gc;
            size_t o0 = ((size_t)h * SEQ + qg) * MAXL + c;
            size_t o1 = ((size_t)h * SEQ + qg + 8) * MAXL + c;
            *(float2*)(scores + o0) =
                make_float2(acc[mi][ni][0] * scale, acc[mi][ni][1] * scale);
            *(float2*)(scores + o1) =
                make_float2(acc[mi][ni][2] * scale, acc[mi][ni][3] * scale);
        }
    }
}

// ===================== softmax -> P hi/lo bf16 ==============================
__global__ void softmax_psplit(float* __restrict__ scores,
                               const int* __restrict__ cu, int nseg,
                               __nv_bfloat16* __restrict__ ph,
                               __nv_bfloat16* __restrict__ pl) {
    int row = blockIdx.x;
    int q = row % SEQ;
    int L = MAXL;
    for (int s = 0; s < nseg; s++)
        if (q >= cu[s] && q < cu[s + 1]) { L = cu[s + 1] - cu[s]; break; }
    float* r = scores + (size_t)row * MAXL;
    int tid = threadIdx.x;
    __shared__ float red[256];
    float m = -3.4e38f;
    for (int i = tid; i < L; i += 256) m = fmaxf(m, r[i]);
    red[tid] = m;
    __syncthreads();
    for (int s = 128; s > 0; s >>= 1) {
        if (tid < s) red[tid] = fmaxf(red[tid], red[tid + s]);
        __syncthreads();
    }
    m = red[0];
    __syncthreads();
    float sum = 0.f;
    for (int i = tid; i < L; i += 256) {
        float e = expf(r[i] - m);
        r[i] = e;
        sum += e;
    }
    red[tid] = sum;
    __syncthreads();
    for (int s = 128; s > 0; s >>= 1) {
        if (tid < s) red[tid] += red[tid + s];
        __syncthreads();
    }
    float inv = 1.f / red[0];
    for (int i = tid; i < L; i += 256) {
        float p = r[i] * inv;
        __nv_bfloat16 hh, ll;
        split_bf16(p, hh, ll);
        ph[(size_t)row * MAXL + i] = hh;
        pl[(size_t)row * MAXL + i] = ll;
    }
}

// ===================== attention P@V ========================================
__device__ __forceinline__ void load_chunk_pv(
    uint32_t buf, int tid,
    const __nv_bfloat16* __restrict__ Ph, const __nv_bfloat16* __restrict__ Pl,
    const __nv_bfloat16* __restrict__ Vh, const __nv_bfloat16* __restrict__ Vl,
    int k0) {
#pragma unroll
    for (int t = 0; t < 16; t++) {
        int idx = tid + t * 256;
        int tile = idx >> 10;
        int w = idx & 1023;
        if (tile < 2) {
            int r = w >> 3, c8 = w & 7;
            const __nv_bfloat16* src = (tile == 0) ? Ph : Pl;
            uint32_t dst = buf + tile * 16384 + sw128((uint32_t)(r * 128 + c8 * 16));
            cp_async16(dst, src + (size_t)r * MAXL + k0 + c8 * 8);
        } else {
            int r = w >> 4, c = w & 15;
            const __nv_bfloat16* src = (tile == 2) ? Vh : Vl;
            uint32_t dst = buf + 32768 + (tile - 2) * 16384 +
                           sw128((uint32_t)(r * 256 + c * 16));
            cp_async16(dst, src + (size_t)(k0 + r) * HD + c * 8);
        }
    }
}

__global__ __launch_bounds__(256, 1) void attn_pv_mma(
    const __nv_bfloat16* __restrict__ Ph, const __nv_bfloat16* __restrict__ Pl,
    const __nv_bfloat16* __restrict__ Vh, const __nv_bfloat16* __restrict__ Vl,
    const int* __restrict__ cu, int nseg,
    __nv_bfloat16* __restrict__ oh, __nv_bfloat16* __restrict__ ol) {
    extern __shared__ char smem[];
    const uint32_t sb = smem_to_u32(smem);
    const int h = blockIdx.z / nseg, s = blockIdx.z % nseg;
    const int s0 = cu[s];
    const int L = cu[s + 1] - s0;
    const int q0 = blockIdx.y * 128;
    if (q0 >= L) return;
    const int tid = threadIdx.x;
    const int wid = tid >> 5, lane = tid & 31;
    const int wm = wid & 1, wn = wid >> 1;

    const __nv_bfloat16* ph = Ph + ((size_t)h * SEQ + s0 + q0) * MAXL;
    const __nv_bfloat16* pl = Pl + ((size_t)h * SEQ + s0 + q0) * MAXL;
    const __nv_bfloat16* vh = Vh + ((size_t)h * SEQ + s0) * HD;
    const __nv_bfloat16* vl = Vl + ((size_t)h * SEQ + s0) * HD;

    float acc[4][4][4];
#pragma unroll
    for (int i = 0; i < 4; i++)
#pragma unroll
        for (int j = 0; j < 4; j++)
#pragma unroll
            for (int k = 0; k < 4; k++) acc[i][j][k] = 0.f;

    const int nch = L >> 6;
    load_chunk_pv(sb, tid, ph, pl, vh, vl, 0);
    CP_COMMIT();
    for (int i = 0; i < nch; i++) {
        if (i + 1 < nch) {
            load_chunk_pv(sb + ((i + 1) & 1) * 65536, tid, ph, pl, vh, vl, (i + 1) << 6);
            CP_COMMIT();
            CP_WAIT1();
        } else {
            CP_WAIT0();
        }
        __syncthreads();
        {
            const uint32_t buf = sb + (i & 1) * 65536;
            const uint32_t bAh = buf;
            const uint32_t bAl = buf + 16384;
            const uint32_t bBh = buf + 32768;
            const uint32_t bBl = buf + 49152;
#pragma unroll
            for (int ks = 0; ks < 4; ks++) {
                uint32_t bh[4][2], bl[4][2];
#pragma unroll
                for (int ni = 0; ni < 4; ni++) {
                    uint32_t nb = (wn * 32 + ni * 8) * 2;
                    uint32_t sw = sw128((ks * 16 + (lane & 15)) * 256 + nb);
                    ldsm2t(bh[ni], bBh + sw);
                    ldsm2t(bl[ni], bBl + sw);
                }
#pragma unroll
                for (int mi = 0; mi < 4; mi++) {
                    uint32_t rowA = wm * 64 + mi * 16 + (lane & 15);
                    uint32_t kb = ks * 32 + (lane >> 4) * 16;
                    uint32_t sw = sw128(rowA * 128 + kb);
                    uint32_t ah[4], al[4];
                    ldsm4(ah, bAh + sw);
                    ldsm4(al, bAl + sw);
#pragma unroll
                    for (int ni = 0; ni < 4; ni++) {
                        mma_bf16(acc[mi][ni], ah, bh[ni]);
                        mma_bf16(acc[mi][ni], ah, bl[ni]);
                        mma_bf16(acc[mi][ni], al, bh[ni]);
                    }
                }
            }
        }
        __syncthreads();
    }

    const int gr = lane >> 2;
    const int gc = (lane & 3) * 2;
#pragma unroll
    for (int mi = 0; mi < 4; mi++) {
        int qg = s0 + q0 + wm * 64 + mi * 16 + gr;
#pragma unroll
        for (int ni = 0; ni < 4; ni++) {
            int d = wn * 32 + ni * 8 + gc;
            size_t o0 = (size_t)qg * HID + h * HD + d;
            size_t o1 = (size_t)(qg + 8) * HID + h * HD + d;
            __nv_bfloat16 hh, ll;
            split_bf16(acc[mi][ni][0], hh, ll); oh[o0] = hh; ol[o0] = ll;
            split_bf16(acc[mi][ni][1], hh, ll); oh[o0 + 1] = hh; ol[o0 + 1] = ll;
            split_bf16(acc[mi][ni][2], hh, ll); oh[o1] = hh; ol[o1] = ll;
            split_bf16(acc[mi][ni][3], hh, ll); oh[o1 + 1] = hh; ol[o1 + 1] = ll;
        }
    }
}

// ===================== RMSNorm -> bf16 hi/lo ================================
__global__ void rmsnorm_split(const float* __restrict__ x, const float* __restrict__ w,
                              __nv_bfloat16* __restrict__ yh, __nv_bfloat16* __restrict__ yl) {
    int row = blockIdx.x;
    const float* xr = x + (size_t)row * HID;
    int tid = threadIdx.x;
    float ss = 0.f;
    for (int i = tid; i < HID; i += 256) { float v = xr[i]; ss += v * v; }
    __shared__ float red[256];
    red[tid] = ss;
    __syncthreads();
    for (int s = 128; s > 0; s >>= 1) {
        if (tid < s) red[tid] += red[tid + s];
        __syncthreads();
    }
    float inv = rsqrtf(red[0] / (float)HID + EPS);
    for (int i = tid; i < HID; i += 256) {
        float v = xr[i] * inv * w[i];
        __nv_bfloat16 h, l;
        split_bf16(v, h, l);
        yh[(size_t)row * HID + i] = h;
        yl[(size_t)row * HID + i] = l;
    }
}

// ===================== RoPE + per-head split ================================
__global__ void rope_split(const float* __restrict__ qkv, const float* __restrict__ rot,
                           __nv_bfloat16* __restrict__ qh, __nv_bfloat16* __restrict__ ql,
                           __nv_bfloat16* __restrict__ kh, __nv_bfloat16* __restrict__ kl,
                           __nv_bfloat16* __restrict__ vh, __nv_bfloat16* __restrict__ vl) {
    int n = blockIdx.x, h = blockIdx.y, d = threadIdx.x;
    float ang = rot[n * HD + d];
    float c = cosf(ang), s = sinf(ang);
    const float* q = qkv + (size_t)n * QKVW + h * HD;
    const float* k = q + HID;
    const float* v = q + 2 * HID;
    int p = (d < 64) ? d + 64 : d - 64;
    float sgn = (d < 64) ? -1.f : 1.f;
    float qr = q[d] * c + sgn * q[p] * s;
    float kr = k[d] * c + sgn * k[p] * s;
    float vv = v[d];
    size_t o = ((size_t)h * SEQ + n) * HD + d;
    __nv_bfloat16 hh, ll;
    split_bf16(qr, hh, ll); qh[o] = hh; ql[o] = ll;
    split_bf16(kr, hh, ll); kh[o] = hh; kl[o] = ll;
    split_bf16(vv, hh, ll); vh[o] = hh; vl[o] = ll;
}

// ===================== host orchestration ===================================
extern "C" void kernel_launch(void* const* d_in, const int* in_sizes, int n_in,
                              void* d_out, int out_size) {
    const float* hidden = (const float*)d_in[0];
    const float* rot    = (const float*)d_in[1];
    const float* n1w    = (const float*)d_in[2];
    const float* n2w    = (const float*)d_in[3];
    const float* qkv_w  = (const float*)d_in[4];
    const float* proj_w = (const float*)d_in[5];
    const float* gate_w = (const float*)d_in[6];
    const float* up_w   = (const float*)d_in[7];
    const float* down_w = (const float*)d_in[8];
    const int*   cu     = (const int*)d_in[9];
    float* out = (float*)d_out;
    int nseg = in_sizes[9] - 1;

    const int ATTN_SMEM = 2 * 65536;
    const int SMEM256 = 2 * STG256;
    cudaFuncSetAttribute(gemm_bf16x3_256, cudaFuncAttributeMaxDynamicSharedMemorySize, SMEM256);
    cudaFuncSetAttribute(gemm_swiglu_dual256, cudaFuncAttributeMaxDynamicSharedMemorySize, SMEM256);
    cudaFuncSetAttribute(attn_qk, cudaFuncAttributeMaxDynamicSharedMemorySize, ATTN_SMEM);
    cudaFuncSetAttribute(attn_pv_mma, cudaFuncAttributeMaxDynamicSharedMemorySize, ATTN_SMEM);

    float *p_qkv, *p_scores, *p_hid2;
    cudaGetSymbolAddress((void**)&p_qkv,    g_qkv);
    cudaGetSymbolAddress((void**)&p_scores, g_scores);
    cudaGetSymbolAddress((void**)&p_hid2,   g_hid2);
    __nv_bfloat16 *hn_h, *hn_l, *h2n_h, *h2n_l, *at_h, *at_l, *act_h, *act_l;
    __nv_bfloat16 *q_h, *q_l, *k_h, *k_l, *v_h, *v_l, *pp_h, *pp_l;
    __nv_bfloat16 *wq_h, *wq_l, *wp_h, *wp_l, *wg_h, *wg_l, *wu_h, *wu_l, *wd_h, *wd_l;
    cudaGetSymbolAddress((void**)&hn_h, g_hn_h);   cudaGetSymbolAddress((void**)&hn_l, g_hn_l);
    cudaGetSymbolAddress((void**)&h2n_h, g_h2n_h); cudaGetSymbolAddress((void**)&h2n_l, g_h2n_l);
    cudaGetSymbolAddress((void**)&at_h, g_at_h);   cudaGetSymbolAddress((void**)&at_l, g_at_l);
    cudaGetSymbolAddress((void**)&act_h, g_act_h); cudaGetSymbolAddress((void**)&act_l, g_act_l);
    cudaGetSymbolAddress((void**)&q_h, g_q_h);     cudaGetSymbolAddress((void**)&q_l, g_q_l);
    cudaGetSymbolAddress((void**)&k_h, g_k_h);     cudaGetSymbolAddress((void**)&k_l, g_k_l);
    cudaGetSymbolAddress((void**)&v_h, g_v_h);     cudaGetSymbolAddress((void**)&v_l, g_v_l);
    cudaGetSymbolAddress((void**)&pp_h, g_p_h);    cudaGetSymbolAddress((void**)&pp_l, g_p_l);
    cudaGetSymbolAddress((void**)&wq_h, g_wqkv_h); cudaGetSymbolAddress((void**)&wq_l, g_wqkv_l);
    cudaGetSymbolAddress((void**)&wp_h, g_wproj_h);cudaGetSymbolAddress((void**)&wp_l, g_wproj_l);
    cudaGetSymbolAddress((void**)&wg_h, g_wgate_h);cudaGetSymbolAddress((void**)&wg_l, g_wgate_l);
    cudaGetSymbolAddress((void**)&wu_h, g_wup_h);  cudaGetSymbolAddress((void**)&wu_l, g_wup_l);
    cudaGetSymbolAddress((void**)&wd_h, g_wdown_h);cudaGetSymbolAddress((void**)&wd_l, g_wdown_l);

    dim3 tb(32, 8);
    wconv_t<<<dim3(QKVW / 32, HID / 32), tb>>>(qkv_w, wq_h, wq_l, HID, QKVW);
    wconv_t<<<dim3(HID / 32, HID / 32), tb>>>(proj_w, wp_h, wp_l, HID, HID);
    wconv_t<<<dim3(INTER / 32, HID / 32), tb>>>(gate_w, wg_h, wg_l, HID, INTER);
    wconv_t<<<dim3(INTER / 32, HID / 32), tb>>>(up_w, wu_h, wu_l, HID, INTER);
    wconv_t<<<dim3(HID / 32, INTER / 32), tb>>>(down_w, wd_h, wd_l, INTER, HID);

    // 1. norm1
    rmsnorm_split<<<SEQ, 256>>>(hidden, n1w, hn_h, hn_l);
    // 2. qkv (256-row tiles)
    gemm_bf16x3_256<<<dim3(SEQ / 256, QKVW / 128), 256, SMEM256>>>(
        hn_h, hn_l, wq_h, wq_l, nullptr, p_qkv, QKVW, HID);
    // 3. rope + per-head bf16 split
    rope_split<<<dim3(SEQ, NH), HD>>>(p_qkv, rot, q_h, q_l, k_h, k_l, v_h, v_l);
    // 4. scores
    attn_qk<<<dim3(MAXL / 128, MAXL / 128, NH * nseg), 256, ATTN_SMEM>>>(
        q_h, q_l, k_h, k_l, cu, nseg, p_scores);
    // 5. softmax -> P hi/lo
    softmax_psplit<<<NH * SEQ, 256>>>(p_scores, cu, nseg, pp_h, pp_l);
    // 6. O = P @ V
    attn_pv_mma<<<dim3(1, MAXL / 128, NH * nseg), 256, ATTN_SMEM>>>(
        pp_h, pp_l, v_h, v_l, cu, nseg, at_h, at_l);
    // 7. hid2 = attn @ proj_w + hidden (256-row tiles)
    gemm_bf16x3_256<<<dim3(SEQ / 256, HID / 128), 256, SMEM256>>>(
        at_h, at_l, wp_h, wp_l, hidden, p_hid2, HID, HID);
    // 8. norm2
    rmsnorm_split<<<SEQ, 256>>>(p_hid2, n2w, h2n_h, h2n_l);
    // 9. fused gate+up+swiglu (256x64 tiles) -> act hi/lo
    gemm_swiglu_dual256<<<dim3(SEQ / 256, INTER / 64), 256, SMEM256>>>(
        h2n_h, h2n_l, wg_h, wg_l, wu_h, wu_l, act_h, act_l, INTER, HID);
    // 10. out = act @ down_w + hid2 (256-row tiles)
    gemm_bf16x3_256<<<dim3(SEQ / 256, HID / 128), 256, SMEM256>>>(
        act_h, act_l, wd_h, wd_l, p_hid2, out, HID, INTER);
}

// round 13
// speedup vs baseline: 2.8031x; 1.0461x over previous
#include <cuda_runtime.h>
#include <cuda_bf16.h>
#include <cstdint>
#include <math.h>

#define SEQ    3072
#define HID    1536
#define NH     12
#define HD     128
#define QKVW   4608   // 3*HID
#define INTER  13696
#define MAXL   1024
#define EPS    1e-6f

// ===================== PTX helpers (baseline PTX only) ======================
__device__ __forceinline__ uint32_t smem_to_u32(const void* p) {
    uint32_t a;
    asm("{ .reg .u64 t; cvta.to.shared.u64 t, %1; cvt.u32.u64 %0, t; }"
        : "=r"(a) : "l"(p));
    return a;
}
__device__ __forceinline__ void cp_async16(uint32_t dst, const void* src) {
    asm volatile("cp.async.cg.shared.global [%0], [%1], 16;"
                 :: "r"(dst), "l"(src) : "memory");
}
#define CP_COMMIT() asm volatile("cp.async.commit_group;" ::: "memory")
#define CP_WAIT1()  asm volatile("cp.async.wait_group 1;" ::: "memory")
#define CP_WAIT0()  asm volatile("cp.async.wait_group 0;" ::: "memory")

__device__ __forceinline__ void ldsm4(uint32_t* r, uint32_t addr) {
    asm volatile("ldmatrix.sync.aligned.m8n8.x4.shared.b16 {%0,%1,%2,%3}, [%4];"
                 : "=r"(r[0]), "=r"(r[1]), "=r"(r[2]), "=r"(r[3]) : "r"(addr));
}
__device__ __forceinline__ void ldsm2(uint32_t* r, uint32_t addr) {
    asm volatile("ldmatrix.sync.aligned.m8n8.x2.shared.b16 {%0,%1}, [%2];"
                 : "=r"(r[0]), "=r"(r[1]) : "r"(addr));
}
__device__ __forceinline__ void ldsm2t(uint32_t* r, uint32_t addr) {
    asm volatile("ldmatrix.sync.aligned.m8n8.x2.trans.shared.b16 {%0,%1}, [%2];"
                 : "=r"(r[0]), "=r"(r[1]) : "r"(addr));
}
__device__ __forceinline__ void mma_bf16(float* c, const uint32_t* a, const uint32_t* b) {
    asm volatile("mma.sync.aligned.m16n8k16.row.col.f32.bf16.bf16.f32 "
                 "{%0,%1,%2,%3}, {%4,%5,%6,%7}, {%8,%9}, {%0,%1,%2,%3};"
                 : "+f"(c[0]), "+f"(c[1]), "+f"(c[2]), "+f"(c[3])
                 : "r"(a[0]), "r"(a[1]), "r"(a[2]), "r"(a[3]),
                   "r"(b[0]), "r"(b[1]));
}
__device__ __forceinline__ void split_bf16(float v, __nv_bfloat16& h, __nv_bfloat16& l) {
    h = __float2bfloat16(v);
    l = __float2bfloat16(v - __bfloat162float(h));
}
// pack two floats into bf16x2 reg (x -> low, y -> high), plus lo-residual pack
__device__ __forceinline__ uint32_t pack_bf16x2(float x, float y) {
    __nv_bfloat162 t;
    t.x = __float2bfloat16(x);
    t.y = __float2bfloat16(y);
    return *reinterpret_cast<uint32_t*>(&t);
}
__device__ __forceinline__ uint32_t pack_bf16x2_lo(float x, float y) {
    float xh = __bfloat162float(__float2bfloat16(x));
    float yh = __bfloat162float(__float2bfloat16(y));
    __nv_bfloat162 t;
    t.x = __float2bfloat16(x - xh);
    t.y = __float2bfloat16(y - yh);
    return *reinterpret_cast<uint32_t*>(&t);
}
__device__ __forceinline__ uint32_t sw128(uint32_t off) {
    return off ^ ((off >> 3) & 0x70);
}

// ===================== scratch =============================================
__device__ float g_qkv   [SEQ * QKVW];
__device__ float g_hid2  [SEQ * HID];

__device__ __nv_bfloat16 g_hn_h [SEQ * HID],  g_hn_l [SEQ * HID];
__device__ __nv_bfloat16 g_h2n_h[SEQ * HID],  g_h2n_l[SEQ * HID];
__device__ __nv_bfloat16 g_at_h [SEQ * HID],  g_at_l [SEQ * HID];
__device__ __nv_bfloat16 g_act_h[(size_t)SEQ * INTER], g_act_l[(size_t)SEQ * INTER];

__device__ __nv_bfloat16 g_q_h[(size_t)NH * SEQ * HD], g_q_l[(size_t)NH * SEQ * HD];
__device__ __nv_bfloat16 g_k_h[(size_t)NH * SEQ * HD], g_k_l[(size_t)NH * SEQ * HD];
__device__ __nv_bfloat16 g_v_h[(size_t)NH * SEQ * HD], g_v_l[(size_t)NH * SEQ * HD];

__device__ __nv_bfloat16 g_wqkv_h [(size_t)QKVW * HID],  g_wqkv_l [(size_t)QKVW * HID];
__device__ __nv_bfloat16 g_wproj_h[(size_t)HID * HID],   g_wproj_l[(size_t)HID * HID];
__device__ __nv_bfloat16 g_wgate_h[(size_t)INTER * HID], g_wgate_l[(size_t)INTER * HID];
__device__ __nv_bfloat16 g_wup_h  [(size_t)INTER * HID], g_wup_l  [(size_t)INTER * HID];
__device__ __nv_bfloat16 g_wdown_h[(size_t)HID * INTER], g_wdown_l[(size_t)HID * INTER];

// ===================== weight transpose + split =============================
__global__ void wconv_t(const float* __restrict__ W, __nv_bfloat16* __restrict__ Th,
                        __nv_bfloat16* __restrict__ Tl, int K, int N) {
    __shared__ float ts[32][33];
    int n0 = blockIdx.x * 32, k0 = blockIdx.y * 32;
    int tx = threadIdx.x, ty = threadIdx.y;   // 32 x 8
#pragma unroll
    for (int r = 0; r < 32; r += 8)
        ts[ty + r][tx] = W[(size_t)(k0 + ty + r) * N + n0 + tx];
    __syncthreads();
#pragma unroll
    for (int r = 0; r < 32; r += 8) {
        float v = ts[tx][ty + r];
        __nv_bfloat16 h, l;
        split_bf16(v, h, l);
        size_t o = (size_t)(n0 + ty + r) * K + k0 + tx;
        Th[o] = h;
        Tl[o] = l;
    }
}

// ===================== shared GEMM machinery (k=64 chunks) ==================
__device__ __forceinline__ void load_chunk(
    uint32_t buf, int tid,
    const __nv_bfloat16* __restrict__ Ah, const __nv_bfloat16* __restrict__ Al,
    const __nv_bfloat16* __restrict__ Bh, const __nv_bfloat16* __restrict__ Bl,
    int m0, int n0, int k0, int K) {
#pragma unroll
    for (int t = 0; t < 16; t++) {
        int idx = tid + t * 256;
        int tile = idx >> 10;
        int w = idx & 1023;
        int r = w >> 3, c8 = w & 7;
        const __nv_bfloat16* src =
            (tile == 0 ? Ah : tile == 1 ? Al : tile == 2 ? Bh : Bl);
        int row = (tile < 2 ? m0 : n0) + r;
        uint32_t dst = buf + tile * 16384 + sw128((uint32_t)(r * 128 + c8 * 16));
        cp_async16(dst, src + (size_t)row * K + k0 + c8 * 8);
    }
}

__device__ __forceinline__ void compute_chunk(
    uint32_t buf, int wm, int wn, int lane, float acc[4][4][4]) {
    const uint32_t bAh = buf;
    const uint32_t bAl = buf + 16384;
    const uint32_t bBh = buf + 32768;
    const uint32_t bBl = buf + 49152;
#pragma unroll
    for (int ks = 0; ks < 4; ks++) {
        uint32_t bh[4][2], bl[4][2];
#pragma unroll
        for (int ni = 0; ni < 4; ni++) {
            uint32_t rowB = wn * 32 + ni * 8 + (lane & 7);
            uint32_t kb = ks * 32 + ((lane >> 3) & 1) * 16;
            uint32_t sw = sw128(rowB * 128 + kb);
            ldsm2(bh[ni], bBh + sw);
            ldsm2(bl[ni], bBl + sw);
        }
#pragma unroll
        for (int mi = 0; mi < 4; mi++) {
            uint32_t rowA = wm * 64 + mi * 16 + (lane & 15);
            uint32_t kb = ks * 32 + (lane >> 4) * 16;
            uint32_t sw = sw128(rowA * 128 + kb);
            uint32_t ah[4], al[4];
            ldsm4(ah, bAh + sw);
            ldsm4(al, bAl + sw);
#pragma unroll
            for (int ni = 0; ni < 4; ni++) {
                mma_bf16(acc[mi][ni], ah, bh[ni]);
                mma_bf16(acc[mi][ni], ah, bl[ni]);
                mma_bf16(acc[mi][ni], al, bh[ni]);
            }
        }
    }
}

// ===================== main GEMM (fp32 out, optional residual) ==============
__global__ __launch_bounds__(256, 1) void gemm_bf16x3(
    const __nv_bfloat16* __restrict__ Ah, const __nv_bfloat16* __restrict__ Al,
    const __nv_bfloat16* __restrict__ Bh, const __nv_bfloat16* __restrict__ Bl,
    const float* __restrict__ R, float* __restrict__ C, int N, int K) {
    extern __shared__ char smem[];
    const uint32_t sb = smem_to_u32(smem);
    const int tid = threadIdx.x;
    const int wid = tid >> 5;
    const int lane = tid & 31;
    const int wm = wid & 1;
    const int wn = wid >> 1;
    const int m0 = blockIdx.x * 128;
    const int n0 = blockIdx.y * 128;

    float acc[4][4][4];
#pragma unroll
    for (int i = 0; i < 4; i++)
#pragma unroll
        for (int j = 0; j < 4; j++)
#pragma unroll
            for (int k = 0; k < 4; k++) acc[i][j][k] = 0.f;

    const int nch = K >> 6;
    load_chunk(sb, tid, Ah, Al, Bh, Bl, m0, n0, 0, K);
    CP_COMMIT();
    for (int i = 0; i < nch; i++) {
        if (i + 1 < nch) {
            load_chunk(sb + ((i + 1) & 1) * 65536, tid, Ah, Al, Bh, Bl,
                       m0, n0, (i + 1) << 6, K);
            CP_COMMIT();
            CP_WAIT1();
        } else {
            CP_WAIT0();
        }
        __syncthreads();
        compute_chunk(sb + (i & 1) * 65536, wm, wn, lane, acc);
        __syncthreads();
    }

    const int gr = lane >> 2;
    const int gc = (lane & 3) * 2;
#pragma unroll
    for (int mi = 0; mi < 4; mi++) {
        int r0 = m0 + wm * 64 + mi * 16 + gr;
#pragma unroll
        for (int ni = 0; ni < 4; ni++) {
            int c = n0 + wn * 32 + ni * 8 + gc;
            size_t o0 = (size_t)r0 * N + c;
            size_t o1 = (size_t)(r0 + 8) * N + c;
            float2 v0 = make_float2(acc[mi][ni][0], acc[mi][ni][1]);
            float2 v1 = make_float2(acc[mi][ni][2], acc[mi][ni][3]);
            if (R) {
                float2 rr0 = *(const float2*)(R + o0);
                float2 rr1 = *(const float2*)(R + o1);
                v0.x += rr0.x; v0.y += rr0.y;
                v1.x += rr1.x; v1.y += rr1.y;
            }
            *(float2*)(C + o0) = v0;
            *(float2*)(C + o1) = v1;
        }
    }
}

// ===================== fused gate+up+swiglu dual GEMM =======================
#define DUAL_STAGE 98304
__device__ __forceinline__ void load_chunk_dual(
    uint32_t buf, int tid,
    const __nv_bfloat16* __restrict__ Ah, const __nv_bfloat16* __restrict__ Al,
    const __nv_bfloat16* __restrict__ Gh, const __nv_bfloat16* __restrict__ Gl,
    const __nv_bfloat16* __restrict__ Uh, const __nv_bfloat16* __restrict__ Ul,
    int m0, int n0, int k0, int K) {
#pragma unroll
    for (int t = 0; t < 24; t++) {
        int idx = tid + t * 256;            // 0..6143
        int tile = idx >> 10;               // 0..5
        int w = idx & 1023;
        int r = w >> 3, c8 = w & 7;
        const __nv_bfloat16* src =
            (tile == 0 ? Ah : tile == 1 ? Al : tile == 2 ? Gh :
             tile == 3 ? Gl : tile == 4 ? Uh : Ul);
        int row = (tile < 2 ? m0 : n0) + r;
        uint32_t dst = buf + tile * 16384 + sw128((uint32_t)(r * 128 + c8 * 16));
        cp_async16(dst, src + (size_t)row * K + k0 + c8 * 8);
    }
}

__global__ __launch_bounds__(256, 1) void gemm_swiglu_dual(
    const __nv_bfloat16* __restrict__ Ah, const __nv_bfloat16* __restrict__ Al,
    const __nv_bfloat16* __restrict__ Gh, const __nv_bfloat16* __restrict__ Gl,
    const __nv_bfloat16* __restrict__ Uh, const __nv_bfloat16* __restrict__ Ul,
    __nv_bfloat16* __restrict__ Oh, __nv_bfloat16* __restrict__ Ol,
    int N, int K) {
    extern __shared__ char smem[];
    const uint32_t sb = smem_to_u32(smem);
    const int tid = threadIdx.x;
    const int wid = tid >> 5;
    const int lane = tid & 31;
    const int wm = wid & 1;
    const int wn = wid >> 1;
    const int m0 = blockIdx.x * 128;
    const int n0 = blockIdx.y * 128;

    float ag[4][4][4], au[4][4][4];
#pragma unroll
    for (int i = 0; i < 4; i++)
#pragma unroll
        for (int j = 0; j < 4; j++)
#pragma unroll
            for (int k = 0; k < 4; k++) { ag[i][j][k] = 0.f; au[i][j][k] = 0.f; }

    const int nch = K >> 6;
    load_chunk_dual(sb, tid, Ah, Al, Gh, Gl, Uh, Ul, m0, n0, 0, K);
    CP_COMMIT();
    for (int i = 0; i < nch; i++) {
        if (i + 1 < nch) {
            load_chunk_dual(sb + ((i + 1) & 1) * DUAL_STAGE, tid,
                            Ah, Al, Gh, Gl, Uh, Ul, m0, n0, (i + 1) << 6, K);
            CP_COMMIT();
            CP_WAIT1();
        } else {
            CP_WAIT0();
        }
        __syncthreads();
        {
            const uint32_t buf = sb + (i & 1) * DUAL_STAGE;
            const uint32_t bAh = buf;
            const uint32_t bAl = buf + 16384;
            const uint32_t bGh = buf + 32768;
            const uint32_t bGl = buf + 49152;
            const uint32_t bUh = buf + 65536;
            const uint32_t bUl = buf + 81920;
#pragma unroll
            for (int ks = 0; ks < 4; ks++) {
                uint32_t gh[4][2], gl[4][2], uh[4][2], ul[4][2];
#pragma unroll
                for (int ni = 0; ni < 4; ni++) {
                    uint32_t rowB = wn * 32 + ni * 8 + (lane & 7);
                    uint32_t kb = ks * 32 + ((lane >> 3) & 1) * 16;
                    uint32_t sw = sw128(rowB * 128 + kb);
                    ldsm2(gh[ni], bGh + sw);
                    ldsm2(gl[ni], bGl + sw);
                    ldsm2(uh[ni], bUh + sw);
                    ldsm2(ul[ni], bUl + sw);
                }
#pragma unroll
                for (int mi = 0; mi < 4; mi++) {
                    uint32_t rowA = wm * 64 + mi * 16 + (lane & 15);
                    uint32_t kb = ks * 32 + (lane >> 4) * 16;
                    uint32_t sw = sw128(rowA * 128 + kb);
                    uint32_t ah[4], al[4];
                    ldsm4(ah, bAh + sw);
                    ldsm4(al, bAl + sw);
#pragma unroll
                    for (int ni = 0; ni < 4; ni++) {
                        mma_bf16(ag[mi][ni], ah, gh[ni]);
                        mma_bf16(ag[mi][ni], ah, gl[ni]);
                        mma_bf16(ag[mi][ni], al, gh[ni]);
                        mma_bf16(au[mi][ni], ah, uh[ni]);
                        mma_bf16(au[mi][ni], ah, ul[ni]);
                        mma_bf16(au[mi][ni], al, uh[ni]);
                    }
                }
            }
        }
        __syncthreads();
    }

    const int gr = lane >> 2;
    const int gc = (lane & 3) * 2;
#pragma unroll
    for (int mi = 0; mi < 4; mi++) {
        int r0 = m0 + wm * 64 + mi * 16 + gr;
#pragma unroll
        for (int ni = 0; ni < 4; ni++) {
            int c = n0 + wn * 32 + ni * 8 + gc;
            size_t o0 = (size_t)r0 * N + c;
            size_t o1 = (size_t)(r0 + 8) * N + c;
            float g, u, v;
            __nv_bfloat16 h, l;
            g = ag[mi][ni][0]; u = au[mi][ni][0];
            v = (g / (1.f + expf(-g))) * u;
            split_bf16(v, h, l); Oh[o0] = h; Ol[o0] = l;
            g = ag[mi][ni][1]; u = au[mi][ni][1];
            v = (g / (1.f + expf(-g))) * u;
            split_bf16(v, h, l); Oh[o0 + 1] = h; Ol[o0 + 1] = l;
            g = ag[mi][ni][2]; u = au[mi][ni][2];
            v = (g / (1.f + expf(-g))) * u;
            split_bf16(v, h, l); Oh[o1] = h; Ol[o1] = l;
            g = ag[mi][ni][3]; u = au[mi][ni][3];
            v = (g / (1.f + expf(-g))) * u;
            split_bf16(v, h, l); Oh[o1 + 1] = h; Ol[o1 + 1] = l;
        }
    }
}

// ===================== flash attention ======================================
// One CTA = (head, segment, 128-q block). 8 warps, warp = 16 q-rows.
// smem: Q hi/lo (2 x 32KB, 64-dim chunks) @0; 2 stages @65536 + s*65536:
//   Kh c0@0, c1@8K; Kl c0@16K, c1@24K (64 keys x 64 dims each)
//   Vh @32K, Vl @48K (64 keys x 128 dims, 256B rows)
#define FLASH_SMEM (65536 + 2 * 65536)

__device__ __forceinline__ void flash_load_kv(
    uint32_t bs, int tid,
    const __nv_bfloat16* __restrict__ kh, const __nv_bfloat16* __restrict__ kl,
    const __nv_bfloat16* __restrict__ vh, const __nv_bfloat16* __restrict__ vl,
    int krow0) {
#pragma unroll
    for (int t = 0; t < 16; t++) {
        int idx = tid + t * 256;            // 0..4095
        int tile = idx >> 10;               // 0:Kh 1:Kl 2:Vh 3:Vl
        int u = idx & 1023;
        int r = u >> 4, c = u & 15;
        if (tile < 2) {
            const __nv_bfloat16* src = tile ? kl : kh;
            int chunk = c >> 3;
            uint32_t dst = bs + tile * 16384 + chunk * 8192
                         + sw128((uint32_t)(r * 128 + (c & 7) * 16));
            cp_async16(dst, src + (size_t)(krow0 + r) * HD + c * 8);
        } else {
            const __nv_bfloat16* src = (tile == 2) ? vh : vl;
            uint32_t dst = bs + 32768 + (tile - 2) * 16384
                         + sw128((uint32_t)(r * 256 + c * 16));
            cp_async16(dst, src + (size_t)(krow0 + r) * HD + c * 8);
        }
    }
}

__global__ __launch_bounds__(256, 1) void flash_attn(
    const __nv_bfloat16* __restrict__ Qh, const __nv_bfloat16* __restrict__ Ql,
    const __nv_bfloat16* __restrict__ Kh, const __nv_bfloat16* __restrict__ Kl,
    const __nv_bfloat16* __restrict__ Vh, const __nv_bfloat16* __restrict__ Vl,
    const int* __restrict__ cu, int nseg,
    __nv_bfloat16* __restrict__ oh, __nv_bfloat16* __restrict__ ol) {
    extern __shared__ char smem[];
    const uint32_t sb = smem_to_u32(smem);
    const int h = blockIdx.y / nseg, s = blockIdx.y % nseg;
    const int s0 = cu[s];
    const int L = cu[s + 1] - s0;
    const int q0 = blockIdx.x * 128;
    if (q0 >= L) return;
    const int tid = threadIdx.x;
    const int wid = tid >> 5, lane = tid & 31;
    const float scale = 0.088388347648318447f;

    const __nv_bfloat16* qh = Qh + ((size_t)h * SEQ + s0 + q0) * HD;
    const __nv_bfloat16* ql = Ql + ((size_t)h * SEQ + s0 + q0) * HD;
    const __nv_bfloat16* kh = Kh + ((size_t)h * SEQ + s0) * HD;
    const __nv_bfloat16* kl = Kl + ((size_t)h * SEQ + s0) * HD;
    const __nv_bfloat16* vh = Vh + ((size_t)h * SEQ + s0) * HD;
    const __nv_bfloat16* vl = Vl + ((size_t)h * SEQ + s0) * HD;

    // load Q (hi/lo, 64-dim chunks): 4096 16B units
#pragma unroll
    for (int t = 0; t < 16; t++) {
        int idx = tid + t * 256;
        int half = idx >> 11;               // 0: hi, 1: lo
        int u = idx & 2047;
        int r = u >> 4, c = u & 15;
        int chunk = c >> 3;
        const __nv_bfloat16* src = half ? ql : qh;
        uint32_t dst = sb + half * 32768 + chunk * 16384
                     + sw128((uint32_t)(r * 128 + (c & 7) * 16));
        cp_async16(dst, src + (size_t)r * HD + c * 8);
    }
    CP_COMMIT();

    const int nkt = L >> 6;
    flash_load_kv(sb + 65536, tid, kh, kl, vh, vl, 0);
    CP_COMMIT();

    float O[16][4];
#pragma unroll
    for (int i = 0; i < 16; i++)
#pragma unroll
        for (int j = 0; j < 4; j++) O[i][j] = 0.f;
    float mrow[2] = {-1e30f, -1e30f};
    float lsum[2] = {0.f, 0.f};

    for (int kt = 0; kt < nkt; kt++) {
        if (kt + 1 < nkt) {
            flash_load_kv(sb + 65536 + ((kt + 1) & 1) * 65536, tid,
                          kh, kl, vh, vl, (kt + 1) << 6);
            CP_COMMIT();
            CP_WAIT1();
        } else {
            CP_WAIT0();
        }
        __syncthreads();

        const uint32_t bsK = sb + 65536 + (kt & 1) * 65536;
        const uint32_t bsV = bsK + 32768;

        // ---- S = Q K^T (warp: 16 q-rows x 64 keys) ----
        float S[8][4];
#pragma unroll
        for (int i = 0; i < 8; i++)
#pragma unroll
            for (int j = 0; j < 4; j++) S[i][j] = 0.f;
#pragma unroll
        for (int ks = 0; ks < 8; ks++) {
            const int chunk = ks >> 2;
            uint32_t bh[8][2], bl[8][2];
            uint32_t kbB = (ks & 3) * 32 + ((lane >> 3) & 1) * 16;
#pragma unroll
            for (int ni = 0; ni < 8; ni++) {
                uint32_t rowB = ni * 8 + (lane & 7);
                uint32_t sw = sw128(rowB * 128 + kbB);
                ldsm2(bh[ni], bsK + chunk * 8192 + sw);
                ldsm2(bl[ni], bsK + 16384 + chunk * 8192 + sw);
            }
            uint32_t rowA = wid * 16 + (lane & 15);
            uint32_t kbA = (ks & 3) * 32 + (lane >> 4) * 16;
            uint32_t swa = sw128(rowA * 128 + kbA);
            uint32_t ah[4], al[4];
            ldsm4(ah, sb + chunk * 16384 + swa);
            ldsm4(al, sb + 32768 + chunk * 16384 + swa);
#pragma unroll
            for (int ni = 0; ni < 8; ni++) {
                mma_bf16(S[ni], ah, bh[ni]);
                mma_bf16(S[ni], ah, bl[ni]);
                mma_bf16(S[ni], al, bh[ni]);
            }
        }

        // ---- online softmax (rows warp-local; quad shuffles) ----
#pragma unroll
        for (int i = 0; i < 8; i++)
#pragma unroll
            for (int j = 0; j < 4; j++) S[i][j] *= scale;
#pragma unroll
        for (int r = 0; r < 2; r++) {
            float tm = -1e30f;
#pragma unroll
            for (int ni = 0; ni < 8; ni++) {
                tm = fmaxf(tm, S[ni][2 * r]);
                tm = fmaxf(tm, S[ni][2 * r + 1]);
            }
            tm = fmaxf(tm, __shfl_xor_sync(0xffffffffu, tm, 1));
            tm = fmaxf(tm, __shfl_xor_sync(0xffffffffu, tm, 2));
            float mn = fmaxf(mrow[r], tm);
            float alpha = __expf(mrow[r] - mn);
            mrow[r] = mn;
            float rs = 0.f;
#pragma unroll
            for (int ni = 0; ni < 8; ni++) {
                float p0 = __expf(S[ni][2 * r] - mn);
                float p1 = __expf(S[ni][2 * r + 1] - mn);
                S[ni][2 * r] = p0;
                S[ni][2 * r + 1] = p1;
                rs += p0 + p1;
            }
            lsum[r] = lsum[r] * alpha + rs;
#pragma unroll
            for (int nt = 0; nt < 16; nt++) {
                O[nt][2 * r] *= alpha;
                O[nt][2 * r + 1] *= alpha;
            }
        }

        // ---- O += P V (P from registers; V via ldsm2t) ----
#pragma unroll
        for (int ks = 0; ks < 4; ks++) {
            uint32_t aH[4], aL[4];
            aH[0] = pack_bf16x2(S[2 * ks][0], S[2 * ks][1]);
            aH[1] = pack_bf16x2(S[2 * ks][2], S[2 * ks][3]);
            aH[2] = pack_bf16x2(S[2 * ks + 1][0], S[2 * ks + 1][1]);
            aH[3] = pack_bf16x2(S[2 * ks + 1][2], S[2 * ks + 1][3]);
            aL[0] = pack_bf16x2_lo(S[2 * ks][0], S[2 * ks][1]);
            aL[1] = pack_bf16x2_lo(S[2 * ks][2], S[2 * ks][3]);
            aL[2] = pack_bf16x2_lo(S[2 * ks + 1][0], S[2 * ks + 1][1]);
            aL[3] = pack_bf16x2_lo(S[2 * ks + 1][2], S[2 * ks + 1][3]);
            uint32_t rowsw = (uint32_t)((ks * 16 + (lane & 15)) * 256);
#pragma unroll
            for (int nt = 0; nt < 16; nt++) {
                uint32_t sw = sw128(rowsw + nt * 16);
                uint32_t vb[2], vbl[2];
                ldsm2t(vb, bsV + sw);
                ldsm2t(vbl, bsV + 16384 + sw);
                mma_bf16(O[nt], aH, vb);
                mma_bf16(O[nt], aH, vbl);
                mma_bf16(O[nt], aL, vb);
            }
        }
        __syncthreads();
    }

    // ---- normalize + write ----
    float inv[2];
#pragma unroll
    for (int r = 0; r < 2; r++) {
        float lr = lsum[r];
        lr += __shfl_xor_sync(0xffffffffu, lr, 1);
        lr += __shfl_xor_sync(0xffffffffu, lr, 2);
        inv[r] = 1.f / lr;
    }
    const int gr = lane >> 2;
    const int gc = (lane & 3) * 2;
#pragma unroll
    for (int r = 0; r < 2; r++) {
        int qg = s0 + q0 + wid * 16 + gr + r * 8;
#pragma unroll
        for (int nt = 0; nt < 16; nt++) {
            float v0 = O[nt][2 * r] * inv[r];
            float v1 = O[nt][2 * r + 1] * inv[r];
            size_t o = (size_t)qg * HID + h * HD + nt * 8 + gc;
            __nv_bfloat16 h0, l0, h1, l1;
            split_bf16(v0, h0, l0);
            split_bf16(v1, h1, l1);
            __nv_bfloat162 hh, ll;
            hh.x = h0; hh.y = h1;
            ll.x = l0; ll.y = l1;
            *reinterpret_cast<__nv_bfloat162*>(oh + o) = hh;
            *reinterpret_cast<__nv_bfloat162*>(ol + o) = ll;
        }
    }
}

// ===================== RMSNorm -> bf16 hi/lo ================================
__global__ void rmsnorm_split(const float* __restrict__ x, const float* __restrict__ w,
                              __nv_bfloat16* __restrict__ yh, __nv_bfloat16* __restrict__ yl) {
    int row = blockIdx.x;
    const float* xr = x + (size_t)row * HID;
    int tid = threadIdx.x;
    float ss = 0.f;
    for (int i = tid; i < HID; i += 256) { float v = xr[i]; ss += v * v; }
    __shared__ float red[256];
    red[tid] = ss;
    __syncthreads();
    for (int s = 128; s > 0; s >>= 1) {
        if (tid < s) red[tid] += red[tid + s];
        __syncthreads();
    }
    float inv = rsqrtf(red[0] / (float)HID + EPS);
    for (int i = tid; i < HID; i += 256) {
        float v = xr[i] * inv * w[i];
        __nv_bfloat16 h, l;
        split_bf16(v, h, l);
        yh[(size_t)row * HID + i] = h;
        yl[(size_t)row * HID + i] = l;
    }
}

// ===================== RoPE + per-head split ================================
__global__ void rope_split(const float* __restrict__ qkv, const float* __restrict__ rot,
                           __nv_bfloat16* __restrict__ qh, __nv_bfloat16* __restrict__ ql,
                           __nv_bfloat16* __restrict__ kh, __nv_bfloat16* __restrict__ kl,
                           __nv_bfloat16* __restrict__ vh, __nv_bfloat16* __restrict__ vl) {
    int n = blockIdx.x, h = blockIdx.y, d = threadIdx.x;
    float ang = rot[n * HD + d];
    float c = cosf(ang), s = sinf(ang);
    const float* q = qkv + (size_t)n * QKVW + h * HD;
    const float* k = q + HID;
    const float* v = q + 2 * HID;
    int p = (d < 64) ? d + 64 : d - 64;
    float sgn = (d < 64) ? -1.f : 1.f;
    float qr = q[d] * c + sgn * q[p] * s;
    float kr = k[d] * c + sgn * k[p] * s;
    float vv = v[d];
    size_t o = ((size_t)h * SEQ + n) * HD + d;
    __nv_bfloat16 hh, ll;
    split_bf16(qr, hh, ll); qh[o] = hh; ql[o] = ll;
    split_bf16(kr, hh, ll); kh[o] = hh; kl[o] = ll;
    split_bf16(vv, hh, ll); vh[o] = hh; vl[o] = ll;
}

// ===================== host orchestration ===================================
extern "C" void kernel_launch(void* const* d_in, const int* in_sizes, int n_in,
                              void* d_out, int out_size) {
    const float* hidden = (const float*)d_in[0];
    const float* rot    = (const float*)d_in[1];
    const float* n1w    = (const float*)d_in[2];
    const float* n2w    = (const float*)d_in[3];
    const float* qkv_w  = (const float*)d_in[4];
    const float* proj_w = (const float*)d_in[5];
    const float* gate_w = (const float*)d_in[6];
    const float* up_w   = (const float*)d_in[7];
    const float* down_w = (const float*)d_in[8];
    const int*   cu     = (const int*)d_in[9];
    float* out = (float*)d_out;
    int nseg = in_sizes[9] - 1;

    const int GEMM_SMEM = 2 * 65536;
    const int DUAL_SMEM = 2 * DUAL_STAGE;
    cudaFuncSetAttribute(gemm_bf16x3, cudaFuncAttributeMaxDynamicSharedMemorySize, GEMM_SMEM);
    cudaFuncSetAttribute(gemm_swiglu_dual, cudaFuncAttributeMaxDynamicSharedMemorySize, DUAL_SMEM);
    cudaFuncSetAttribute(flash_attn, cudaFuncAttributeMaxDynamicSharedMemorySize, FLASH_SMEM);

    float *p_qkv, *p_hid2;
    cudaGetSymbolAddress((void**)&p_qkv,  g_qkv);
    cudaGetSymbolAddress((void**)&p_hid2, g_hid2);
    __nv_bfloat16 *hn_h, *hn_l, *h2n_h, *h2n_l, *at_h, *at_l, *act_h, *act_l;
    __nv_bfloat16 *q_h, *q_l, *k_h, *k_l, *v_h, *v_l;
    __nv_bfloat16 *wq_h, *wq_l, *wp_h, *wp_l, *wg_h, *wg_l, *wu_h, *wu_l, *wd_h, *wd_l;
    cudaGetSymbolAddress((void**)&hn_h, g_hn_h);   cudaGetSymbolAddress((void**)&hn_l, g_hn_l);
    cudaGetSymbolAddress((void**)&h2n_h, g_h2n_h); cudaGetSymbolAddress((void**)&h2n_l, g_h2n_l);
    cudaGetSymbolAddress((void**)&at_h, g_at_h);   cudaGetSymbolAddress((void**)&at_l, g_at_l);
    cudaGetSymbolAddress((void**)&act_h, g_act_h); cudaGetSymbolAddress((void**)&act_l, g_act_l);
    cudaGetSymbolAddress((void**)&q_h, g_q_h);     cudaGetSymbolAddress((void**)&q_l, g_q_l);
    cudaGetSymbolAddress((void**)&k_h, g_k_h);     cudaGetSymbolAddress((void**)&k_l, g_k_l);
    cudaGetSymbolAddress((void**)&v_h, g_v_h);     cudaGetSymbolAddress((void**)&v_l, g_v_l);
    cudaGetSymbolAddress((void**)&wq_h, g_wqkv_h); cudaGetSymbolAddress((void**)&wq_l, g_wqkv_l);
    cudaGetSymbolAddress((void**)&wp_h, g_wproj_h);cudaGetSymbolAddress((void**)&wp_l, g_wproj_l);
    cudaGetSymbolAddress((void**)&wg_h, g_wgate_h);cudaGetSymbolAddress((void**)&wg_l, g_wgate_l);
    cudaGetSymbolAddress((void**)&wu_h, g_wup_h);  cudaGetSymbolAddress((void**)&wu_l, g_wup_l);
    cudaGetSymbolAddress((void**)&wd_h, g_wdown_h);cudaGetSymbolAddress((void**)&wd_l, g_wdown_l);

    dim3 tb(32, 8);
    wconv_t<<<dim3(QKVW / 32, HID / 32), tb>>>(qkv_w, wq_h, wq_l, HID, QKVW);
    wconv_t<<<dim3(HID / 32, HID / 32), tb>>>(proj_w, wp_h, wp_l, HID, HID);
    wconv_t<<<dim3(INTER / 32, HID / 32), tb>>>(gate_w, wg_h, wg_l, HID, INTER);
    wconv_t<<<dim3(INTER / 32, HID / 32), tb>>>(up_w, wu_h, wu_l, HID, INTER);
    wconv_t<<<dim3(HID / 32, INTER / 32), tb>>>(down_w, wd_h, wd_l, INTER, HID);

    // 1. norm1
    rmsnorm_split<<<SEQ, 256>>>(hidden, n1w, hn_h, hn_l);
    // 2. qkv
    gemm_bf16x3<<<dim3(SEQ / 128, QKVW / 128), 256, GEMM_SMEM>>>(
        hn_h, hn_l, wq_h, wq_l, nullptr, p_qkv, QKVW, HID);
    // 3. rope + per-head bf16 split
    rope_split<<<dim3(SEQ, NH), HD>>>(p_qkv, rot, q_h, q_l, k_h, k_l, v_h, v_l);
    // 4. fused flash attention -> at hi/lo
    flash_attn<<<dim3(MAXL / 128, NH * nseg), 256, FLASH_SMEM>>>(
        q_h, q_l, k_h, k_l, v_h, v_l, cu, nseg, at_h, at_l);
    // 5. hid2 = attn @ proj_w + hidden
    gemm_bf16x3<<<dim3(SEQ / 128, HID / 128), 256, GEMM_SMEM>>>(
        at_h, at_l, wp_h, wp_l, hidden, p_hid2, HID, HID);
    // 6. norm2
    rmsnorm_split<<<SEQ, 256>>>(p_hid2, n2w, h2n_h, h2n_l);
    // 7. fused gate+up+swiglu -> act hi/lo
    gemm_swiglu_dual<<<dim3(SEQ / 128, INTER / 128), 256, DUAL_SMEM>>>(
        h2n_h, h2n_l, wg_h, wg_l, wu_h, wu_l, act_h, act_l, INTER, HID);
    // 8. out = act @ down_w + hid2
    gemm_bf16x3<<<dim3(SEQ / 128, HID / 128), 256, GEMM_SMEM>>>(
        act_h, act_l, wd_h, wd_l, p_hid2, out, HID, INTER);
}